// round 6
// baseline (speedup 1.0000x reference)
#include <cuda_runtime.h>

#define Bv   16
#define Nv   5000
#define Ev   160000
#define Cv   64
#define BNv  80000
#define BEv  2560000
#define ETOTv 2640000
#define OUT_MAIN 5120000   // BNv * Cv
#define NPART 625          // Ev / 256
#define HEADBLKS 40        // ceil(5000/128): gemm blocks that cover nodes < Nv

// ---------------- scratch (static __device__, no allocs) ----------------
__device__ float g_xlS[Nv * Cv];     // xl for nodes < 5000 (message sources)
__device__ float g_aS[Nv];
__device__ float g_aD[Nv];
__device__ int   g_cnt[Nv];
__device__ int   g_off[Nv + 1];
__device__ int   g_cur[Nv];
__device__ int   g_bucket[Ev];       // edge id per CSR slot
__device__ int   g_bsrc[Ev];         // src node per CSR slot
__device__ float g_bval[Ev];         // ea[e]*c per CSR slot
__device__ float g_alphaC[Ev];       // unnormalized p in CSR-slot order
__device__ float g_alphaP[Ev];       // NORMALIZED alpha per unique edge
__device__ float g_selfNorm[Nv];
__device__ float g_part[NPART];
__device__ float g_c;                // sum_k W_edge[k]*att_edge[k]
__device__ float g_meanC;            // mean(edge_attr) * c

// ---------------- f32x2 packed helpers ----------------
__device__ __forceinline__ unsigned long long pk2(float lo, float hi) {
    unsigned long long u;
    asm("mov.b64 %0, {%1, %2};" : "=l"(u) : "f"(lo), "f"(hi));
    return u;
}
__device__ __forceinline__ void fma2(unsigned long long& acc, unsigned long long a, unsigned long long b) {
    asm("fma.rn.f32x2 %0, %1, %2, %3;" : "=l"(acc) : "l"(a), "l"(b), "l"(acc));
}
__device__ __forceinline__ void upk2(unsigned long long u, float& lo, float& hi) {
    asm("mov.b64 {%0, %1}, %2;" : "=f"(lo), "=f"(hi) : "l"(u));
}

// ---------------- fused histogram + edge_attr partial sums ----------------
__global__ void k_histred(const int* __restrict__ ei, const float* __restrict__ ea) {
    int e = blockIdx.x * 256 + threadIdx.x;          // exact: Ev = 625*256
    atomicAdd(&g_cnt[ei[Ev + e]], 1);                // row 1 = dst
    float s = ea[e];
#pragma unroll
    for (int o = 16; o; o >>= 1) s += __shfl_xor_sync(0xffffffffu, s, o);
    __shared__ float sh[8];
    if ((threadIdx.x & 31) == 0) sh[threadIdx.x >> 5] = s;
    __syncthreads();
    if (threadIdx.x < 8) {
        float v = sh[threadIdx.x];
#pragma unroll
        for (int o = 4; o; o >>= 1) v += __shfl_xor_sync(0xffu, v, o);
        if (threadIdx.x == 0) g_part[blockIdx.x] = v;
    }
}

// ------- fused: reduce partials + compute c + exclusive scan (shfl) -------
__global__ void k_scanred(const float* __restrict__ W_edge, const float* __restrict__ att_edge) {
    __shared__ float fred[32];
    __shared__ int   ired[32];
    int t = threadIdx.x;
    int lane = t & 31, w = t >> 5;

    float s = (t < NPART) ? g_part[t] : 0.f;
#pragma unroll
    for (int o = 16; o; o >>= 1) s += __shfl_xor_sync(0xffffffffu, s, o);
    if (lane == 0) fred[w] = s;

    int v[5]; int mysum = 0;
#pragma unroll
    for (int j = 0; j < 5; j++) {
        int i = t * 5 + j;
        v[j] = (i < Nv) ? g_cnt[i] : 0;
        mysum += v[j];
    }
    int inc = mysum;
#pragma unroll
    for (int o = 1; o < 32; o <<= 1) {
        int n = __shfl_up_sync(0xffffffffu, inc, o);
        if (lane >= o) inc += n;
    }
    if (lane == 31) ired[w] = inc;
    __syncthreads();

    if (w == 0) {
        float ps = fred[lane];
#pragma unroll
        for (int o = 16; o; o >>= 1) ps += __shfl_xor_sync(0xffffffffu, ps, o);
        float cv = W_edge[lane] * att_edge[lane] + W_edge[lane + 32] * att_edge[lane + 32];
#pragma unroll
        for (int o = 16; o; o >>= 1) cv += __shfl_xor_sync(0xffffffffu, cv, o);
        if (lane == 0) { g_c = cv; g_meanC = (ps / (float)Ev) * cv; }
        int x = ired[lane];
#pragma unroll
        for (int o = 1; o < 32; o <<= 1) {
            int n = __shfl_up_sync(0xffffffffu, x, o);
            if (lane >= o) x += n;
        }
        ired[lane] = x;
    }
    __syncthreads();

    int base = (w > 0) ? ired[w - 1] : 0;
    int run = base + inc - mysum;
#pragma unroll
    for (int j = 0; j < 5; j++) {
        int i = t * 5 + j;
        if (i < Nv) { g_off[i] = run; g_cur[i] = run; run += v[j]; }
    }
    if (t == 1023) g_off[Nv] = run;
}

__global__ void k_scatter(const int* __restrict__ ei, const float* __restrict__ ea) {
    int e = blockIdx.x * 256 + threadIdx.x;          // exact grid
    int d = ei[Ev + e];
    int s = ei[e];
    float val = ea[e] * g_c;
    int p = atomicAdd(&g_cur[d], 1);
    g_bucket[p] = e;
    g_bsrc[p]   = s;
    g_bval[p]   = val;
}

// ---- dense transform: xl = x @ W^T (+bias into out) + fused attn dots ----
__global__ void __launch_bounds__(256) k_gemm(const float* __restrict__ x,
                                              const float* __restrict__ W,
                                              const float* __restrict__ bias,
                                              const float* __restrict__ attS,
                                              const float* __restrict__ attD,
                                              float* __restrict__ out,
                                              int blockOff) {
    __shared__ float Xs4[16 * 128 * 4];   // 32768 B
    __shared__ float Ws4[16 * 64 * 4];    // 16384 B
    int tid = threadIdx.x;
    int nb = (blockIdx.x + blockOff) * 128;

#pragma unroll
    for (int it = 0; it < 8; it++) {
        int fl = tid + it * 256;
        int row = fl & 127, q = fl >> 7;
        float4 v = *(const float4*)(x + (long long)(nb + row) * 64 + q * 4);
        *(float4*)(Xs4 + q * 512 + row * 4) = v;
    }
#pragma unroll
    for (int it = 0; it < 4; it++) {
        int fl = tid + it * 256;
        int col = fl & 63, q = fl >> 6;
        float4 v = *(const float4*)(W + col * 64 + q * 4);
        *(float4*)(Ws4 + q * 256 + col * 4) = v;
    }
    __syncthreads();

    int tx = tid & 15, ty = tid >> 4;
    int r0 = ty * 8, c0 = tx * 4;

    unsigned long long accp[4][4];
#pragma unroll
    for (int p = 0; p < 4; p++)
#pragma unroll
        for (int j = 0; j < 4; j++) accp[p][j] = 0ull;

#pragma unroll
    for (int q = 0; q < 16; q++) {
        unsigned long long bp[4][4];
#pragma unroll
        for (int j = 0; j < 4; j++) {
            float4 b = *(const float4*)(Ws4 + q * 256 + (c0 + j) * 4);
            const float* bf = (const float*)&b;
#pragma unroll
            for (int kin = 0; kin < 4; kin++) bp[kin][j] = pk2(bf[kin], bf[kin]);
        }
#pragma unroll
        for (int p = 0; p < 4; p++) {
            float4 a0 = *(const float4*)(Xs4 + q * 512 + (r0 + 2 * p) * 4);
            float4 a1 = *(const float4*)(Xs4 + q * 512 + (r0 + 2 * p + 1) * 4);
            const float* a0f = (const float*)&a0;
            const float* a1f = (const float*)&a1;
#pragma unroll
            for (int kin = 0; kin < 4; kin++) {
                unsigned long long ap = pk2(a0f[kin], a1f[kin]);
#pragma unroll
                for (int j = 0; j < 4; j++) fma2(accp[p][j], ap, bp[kin][j]);
            }
        }
    }

    float acc[8][4];
#pragma unroll
    for (int p = 0; p < 4; p++)
#pragma unroll
        for (int j = 0; j < 4; j++) upk2(accp[p][j], acc[2 * p][j], acc[2 * p + 1][j]);

    float4 bb = *(const float4*)(bias + c0);
#pragma unroll
    for (int i = 0; i < 8; i++) {
        int n = nb + r0 + i;
        float4 o;
        o.x = acc[i][0] + bb.x; o.y = acc[i][1] + bb.y;
        o.z = acc[i][2] + bb.z; o.w = acc[i][3] + bb.w;
        *(float4*)(out + (long long)n * 64 + c0) = o;
        if (n < Nv) {
            float4 xo;
            xo.x = acc[i][0]; xo.y = acc[i][1]; xo.z = acc[i][2]; xo.w = acc[i][3];
            *(float4*)(&g_xlS[n * 64 + c0]) = xo;
        }
    }
    if (nb < Nv) {
        float4 as4 = *(const float4*)(attS + c0);
        float4 ad4 = *(const float4*)(attD + c0);
        float ps[8], pd[8];
#pragma unroll
        for (int i = 0; i < 8; i++) {
            ps[i] = acc[i][0] * as4.x + acc[i][1] * as4.y + acc[i][2] * as4.z + acc[i][3] * as4.w;
            pd[i] = acc[i][0] * ad4.x + acc[i][1] * ad4.y + acc[i][2] * ad4.z + acc[i][3] * ad4.w;
        }
#pragma unroll
        for (int o = 8; o > 0; o >>= 1) {
#pragma unroll
            for (int i = 0; i < 8; i++) {
                ps[i] += __shfl_xor_sync(0xffffffffu, ps[i], o);
                pd[i] += __shfl_xor_sync(0xffffffffu, pd[i], o);
            }
        }
        if (tx == 0) {
#pragma unroll
            for (int i = 0; i < 8; i++) {
                int n = nb + r0 + i;
                if (n < Nv) { g_aS[n] = ps[i]; g_aD[n] = pd[i]; }
            }
        }
    }
}

// ------- per-destination softmax + aggregation: ONE WARP PER DST -------
__global__ void __launch_bounds__(256) k_dst(const float* __restrict__ bias,
                                             float* __restrict__ out) {
    int wIdx = threadIdx.x >> 5;                 // warp within block (0..7)
    int d = blockIdx.x * 8 + wIdx;               // destination node
    int lane = threadIdx.x & 31;
    if (d >= Nv) return;
    int s0 = g_off[d], s1 = g_off[d + 1];
    float aDd = g_aD[d];
    float pSelf;
    {
        float xv = g_aS[d] + aDd + g_meanC;
        xv = xv > 0.f ? xv : 0.2f * xv;
        pSelf = __expf(xv);
    }
    __shared__ float sP[8][32];
    __shared__ int   sS[8][32];
    float a0x = 0.f, a0y = 0.f, a1x = 0.f, a1y = 0.f;
    float a2x = 0.f, a2y = 0.f, a3x = 0.f, a3y = 0.f;
    float psum = 0.f;
    for (int base = s0; base < s1; base += 32) {
        int m = s1 - base; if (m > 32) m = 32;
        if (lane < m) {
            int idx = base + lane;
            int s = g_bsrc[idx];
            float xv = g_aS[s] + aDd + g_bval[idx];
            xv = xv > 0.f ? xv : 0.2f * xv;
            float p = __expf(xv);
            psum += p;
            sP[wIdx][lane] = p;
            sS[wIdx][lane] = s;
            g_alphaC[idx] = p;                   // coalesced CSR-order store
        }
        __syncwarp();
        int j = 0;
        for (; j + 4 <= m; j += 4) {
            float p0 = sP[wIdx][j],     p1 = sP[wIdx][j + 1];
            float p2 = sP[wIdx][j + 2], p3 = sP[wIdx][j + 3];
            int   q0 = sS[wIdx][j],     q1 = sS[wIdx][j + 1];
            int   q2 = sS[wIdx][j + 2], q3 = sS[wIdx][j + 3];
            float2 v0 = *(const float2*)(g_xlS + q0 * 64 + lane * 2);
            float2 v1 = *(const float2*)(g_xlS + q1 * 64 + lane * 2);
            float2 v2 = *(const float2*)(g_xlS + q2 * 64 + lane * 2);
            float2 v3 = *(const float2*)(g_xlS + q3 * 64 + lane * 2);
            a0x += p0 * v0.x; a0y += p0 * v0.y;
            a1x += p1 * v1.x; a1y += p1 * v1.y;
            a2x += p2 * v2.x; a2y += p2 * v2.y;
            a3x += p3 * v3.x; a3y += p3 * v3.y;
        }
        for (; j < m; j++) {
            float p0 = sP[wIdx][j];
            int   q0 = sS[wIdx][j];
            float2 v0 = *(const float2*)(g_xlS + q0 * 64 + lane * 2);
            a0x += p0 * v0.x; a0y += p0 * v0.y;
        }
        __syncwarp();
    }
    float accx = (a0x + a1x) + (a2x + a3x);
    float accy = (a0y + a1y) + (a2y + a3y);
#pragma unroll
    for (int o = 16; o; o >>= 1) psum += __shfl_xor_sync(0xffffffffu, psum, o);
    float denom = (float)Bv * psum + pSelf;
    float rd = 1.f / (denom + 1e-16f);
    float2 xs = *(const float2*)(g_xlS + d * 64 + lane * 2);
    float2 bb = *(const float2*)(bias + lane * 2);
    float2 o2;
    o2.x = ((float)Bv * accx + pSelf * xs.x) * rd + bb.x;
    o2.y = ((float)Bv * accy + pSelf * xs.y) * rd + bb.y;
    *(float2*)(out + (long long)d * 64 + lane * 2) = o2;
    if (lane == 0) g_selfNorm[d] = pSelf * rd;
    // normalized alpha: coalesced read of CSR-order p, scatter to edge order
    for (int idx = s0 + lane; idx < s1; idx += 32)
        g_alphaP[g_bucket[idx]] = g_alphaC[idx] * rd;
}

// ------- tuple tail part 1: src/dst rows, float4 (depends only on ei) -------
__global__ void k_tail_sd(const int* __restrict__ ei, float* __restrict__ outTail) {
    int i = (blockIdx.x * 256 + threadIdx.x) * 4;
    if (i >= 2 * ETOTv) return;
    float4 v;
    if (i < ETOTv) {
        if (i < BEv) {
            int e = i - (i / Ev) * Ev;
            v.x = (float)ei[e]; v.y = (float)ei[e + 1];
            v.z = (float)ei[e + 2]; v.w = (float)ei[e + 3];
        } else {
            float b0 = (float)(i - BEv);
            v.x = b0; v.y = b0 + 1.f; v.z = b0 + 2.f; v.w = b0 + 3.f;
        }
    } else {
        int k = i - ETOTv;
        if (k < BEv) {
            int e = k - (k / Ev) * Ev;
            v.x = (float)ei[Ev + e]; v.y = (float)ei[Ev + e + 1];
            v.z = (float)ei[Ev + e + 2]; v.w = (float)ei[Ev + e + 3];
        } else {
            float b0 = (float)(k - BEv);
            v.x = b0; v.y = b0 + 1.f; v.z = b0 + 2.f; v.w = b0 + 3.f;
        }
    }
    *(float4*)(outTail + i) = v;
}

// ------- tuple tail part 2: alpha, float4 (depends on k_dst) -------
__global__ void k_tail_alpha(float* __restrict__ outA, int totalA) {
    int i = (blockIdx.x * 256 + threadIdx.x) * 4;
    if (i >= totalA) return;
    float4 v;
    if (i < BEv) {
        int e = i - (i / Ev) * Ev;
        v = *(const float4*)(g_alphaP + e);
    } else {
        int d = i - BEv;
        if (d + 3 < Nv) {
            v.x = g_selfNorm[d]; v.y = g_selfNorm[d + 1];
            v.z = g_selfNorm[d + 2]; v.w = g_selfNorm[d + 3];
        } else {
            v.x = (d     < Nv) ? g_selfNorm[d]     : 1.0f;
            v.y = (d + 1 < Nv) ? g_selfNorm[d + 1] : 1.0f;
            v.z = (d + 2 < Nv) ? g_selfNorm[d + 2] : 1.0f;
            v.w = (d + 3 < Nv) ? g_selfNorm[d + 3] : 1.0f;
        }
    }
    *(float4*)(outA + i) = v;
}

// ---------------- launch ----------------
extern "C" void kernel_launch(void* const* d_in, const int* in_sizes, int n_in,
                              void* d_out, int out_size) {
    const float* data   = (const float*)d_in[0];
    const int*   ei     = (const int*)  d_in[1];
    const float* ea     = (const float*)d_in[2];
    const float* W      = (const float*)d_in[3];
    const float* W_edge = (const float*)d_in[4];
    const float* attS   = (const float*)d_in[5];
    const float* attD   = (const float*)d_in[6];
    const float* attE   = (const float*)d_in[7];
    const float* bias   = (const float*)d_in[8];
    float* out = (float*)d_out;

    static cudaStream_t sB = nullptr, sC = nullptr, sD = nullptr;
    static cudaEvent_t eFork = nullptr, eB = nullptr, eC = nullptr, eH = nullptr, eD = nullptr;
    if (!sB) {
        cudaStreamCreateWithFlags(&sB, cudaStreamNonBlocking);
        cudaStreamCreateWithFlags(&sC, cudaStreamNonBlocking);
        cudaStreamCreateWithFlags(&sD, cudaStreamNonBlocking);
        cudaEventCreateWithFlags(&eFork, cudaEventDisableTiming);
        cudaEventCreateWithFlags(&eB, cudaEventDisableTiming);
        cudaEventCreateWithFlags(&eC, cudaEventDisableTiming);
        cudaEventCreateWithFlags(&eH, cudaEventDisableTiming);
        cudaEventCreateWithFlags(&eD, cudaEventDisableTiming);
    }

    void* cntAddr = nullptr;
    cudaGetSymbolAddress(&cntAddr, g_cnt);

    // fork
    cudaEventRecord(eFork, 0);
    cudaStreamWaitEvent(sB, eFork, 0);
    cudaStreamWaitEvent(sC, eFork, 0);
    cudaStreamWaitEvent(sD, eFork, 0);

    // side chain: CSR build
    cudaMemsetAsync(cntAddr, 0, Nv * sizeof(int), sB);
    k_histred<<<NPART, 256, 0, sB>>>(ei, ea);
    k_scanred<<<1, 1024, 0, sB>>>(W_edge, attE);
    k_scatter<<<NPART, 256, 0, sB>>>(ei, ea);
    cudaEventRecord(eB, sB);

    // tail src/dst rows (independent)
    if (out_size > OUT_MAIN) {
        int n4 = (2 * ETOTv) / 4;
        k_tail_sd<<<(n4 + 255) / 256, 256, 0, sC>>>(ei, out + OUT_MAIN);
    }
    cudaEventRecord(eC, sC);

    // gemm head (covers all nodes < Nv) on main stream — gates k_dst
    k_gemm<<<HEADBLKS, 256>>>(data, W, bias, attS, attD, out, 0);
    cudaEventRecord(eH, 0);

    // gemm rest runs concurrently with k_dst on sD
    cudaStreamWaitEvent(sD, eH, 0);
    k_gemm<<<BNv / 128 - HEADBLKS, 256, 0, sD>>>(data, W, bias, attS, attD, out, HEADBLKS);
    cudaEventRecord(eD, sD);

    // main: wait CSR, then dst softmax/aggregate, then alpha tail
    cudaStreamWaitEvent(0, eB, 0);
    k_dst<<<(Nv + 7) / 8, 256>>>(bias, out);

    if (out_size > OUT_MAIN) {
        int totalA = out_size - OUT_MAIN - 2 * ETOTv;
        if (totalA > 0) {
            int n4 = (totalA + 3) / 4;
            k_tail_alpha<<<(n4 + 255) / 256, 256>>>(out + OUT_MAIN + 2 * ETOTv, totalA);
        }
    }

    // join all side streams before capture end
    cudaStreamWaitEvent(0, eC, 0);
    cudaStreamWaitEvent(0, eD, 0);
}

// round 8
// speedup vs baseline: 1.6624x; 1.6624x over previous
#include <cuda_runtime.h>
#include <cuda_bf16.h>
#include <cstdint>

#define Bv   16
#define Nv   5000
#define Ev   160000
#define BNv  80000
#define BEv  2560000
#define ETOTv 2640000
#define OUT_MAIN 5120000   // BNv * 64
#define NPART 625          // Ev / 256
#define CAP  128           // bucket capacity per destination

// ---------------- scratch (static __device__, no allocs) ----------------
__device__ float g_xlS[Nv * 64];
__device__ float g_aS[Nv];
__device__ float g_aD[Nv];
__device__ int   g_bcnt[Nv + 2];     // [Nv] reused as float sum(ea)
__device__ int   g_bsrc[Nv * CAP];
__device__ int   g_bedge[Nv * CAP];
__device__ float g_bval[Nv * CAP];   // raw ea per slot
__device__ float g_alphaP[Ev];       // normalized alpha per unique edge
__device__ float g_selfNorm[Nv];
__device__ uint4 g_Wimg[1152];       // 18432B: W_hi [64][72]bf16 | W_lo [64][72]bf16

// ---------------- helpers ----------------
__device__ __forceinline__ uint32_t smem_to_u32(const void* p) {
    uint32_t a;
    asm("{ .reg .u64 t; cvta.to.shared.u64 t, %1; cvt.u32.u64 %0, t; }" : "=r"(a) : "l"(p));
    return a;
}
__device__ __forceinline__ void bf16_split(float v, unsigned short& h, unsigned short& l) {
    __nv_bfloat16 hb = __float2bfloat16(v);
    __nv_bfloat16 lb = __float2bfloat16(v - __bfloat162float(hb));
    h = *(unsigned short*)&hb;
    l = *(unsigned short*)&lb;
}
#define LDMX4(r, a) \
    asm volatile("ldmatrix.sync.aligned.m8n8.x4.shared.b16 {%0,%1,%2,%3}, [%4];" \
        : "=r"((r)[0]), "=r"((r)[1]), "=r"((r)[2]), "=r"((r)[3]) : "r"(a))
#define LDMX2(r, a) \
    asm volatile("ldmatrix.sync.aligned.m8n8.x2.shared.b16 {%0,%1}, [%2];" \
        : "=r"((r)[0]), "=r"((r)[1]) : "r"(a))
#define MMA16816(c, a, b) \
    asm volatile("mma.sync.aligned.m16n8k16.row.col.f32.bf16.bf16.f32 " \
        "{%0,%1,%2,%3}, {%4,%5,%6,%7}, {%8,%9}, {%0,%1,%2,%3};" \
        : "+f"((c)[0]), "+f"((c)[1]), "+f"((c)[2]), "+f"((c)[3]) \
        : "r"((a)[0]), "r"((a)[1]), "r"((a)[2]), "r"((a)[3]), "r"((b)[0]), "r"((b)[1]))

// smem layout for k_gemm (dynamic): A_hi | A_lo | B_hi | B_lo, rows of 72 bf16 (144B)
#define SA_HI 0
#define SA_LO 18432
#define SB_HI 36864
#define SB_LO 46080
#define SM_TOT 55296

// ---------------- W -> bf16 hi/lo image [64 rows][72 bf16] ----------------
__global__ void k_wconv(const float* __restrict__ W) {
    int tid = threadIdx.x;
    char* img = (char*)g_Wimg;
    for (int p = tid; p < 2048; p += 256) {
        int c = p >> 5, cp = p & 31;
        float2 v = *(const float2*)(W + c * 64 + cp * 2);
        unsigned short h0, l0, h1, l1;
        bf16_split(v.x, h0, l0);
        bf16_split(v.y, h1, l1);
        unsigned hu = (unsigned)h0 | ((unsigned)h1 << 16);
        unsigned lu = (unsigned)l0 | ((unsigned)l1 << 16);
        *(unsigned*)(img + c * 144 + cp * 4) = hu;
        *(unsigned*)(img + 9216 + c * 144 + cp * 4) = lu;
    }
}

// ---- tensor GEMM (mma.sync bf16 split): out = x@W^T + bias; xl, attn dots ----
__global__ void __launch_bounds__(256) k_gemm(const float* __restrict__ x,
                                              const float* __restrict__ bias,
                                              const float* __restrict__ attS,
                                              const float* __restrict__ attD,
                                              float* __restrict__ out) {
    extern __shared__ char sm[];
    int tid = threadIdx.x, wid = tid >> 5, lane = tid & 31;
    int nb = blockIdx.x * 128;

    // stage B (copy prebuilt image)
    {
        uint4* dst = (uint4*)(sm + SB_HI);
        for (int i = tid; i < 1152; i += 256) dst[i] = g_Wimg[i];
    }
    // stage A: convert 128 rows x 64 cols to hi/lo bf16
    for (int p = tid; p < 4096; p += 256) {
        int row = p >> 5, cp = p & 31;
        float2 v = *(const float2*)(x + (size_t)(nb + row) * 64 + cp * 2);
        unsigned short h0, l0, h1, l1;
        bf16_split(v.x, h0, l0);
        bf16_split(v.y, h1, l1);
        unsigned hu = (unsigned)h0 | ((unsigned)h1 << 16);
        unsigned lu = (unsigned)l0 | ((unsigned)l1 << 16);
        *(unsigned*)(sm + SA_HI + row * 144 + cp * 4) = hu;
        *(unsigned*)(sm + SA_LO + row * 144 + cp * 4) = lu;
    }
    __syncthreads();

    uint32_t sbase = smem_to_u32(sm);
    int r0 = wid * 16;
    uint32_t aHi = sbase + SA_HI + (r0 + (lane & 15)) * 144 + (lane >> 4) * 16;
    uint32_t aLo = aHi + (SA_LO - SA_HI);
    uint32_t bRowOff = (lane & 7) * 144 + ((lane >> 3) & 1) * 16;

    float acc[8][4];
#pragma unroll
    for (int nt = 0; nt < 8; nt++)
#pragma unroll
        for (int j = 0; j < 4; j++) acc[nt][j] = 0.f;

#pragma unroll
    for (int kc = 0; kc < 4; kc++) {
        uint32_t ahi[4], alo[4];
        LDMX4(ahi, aHi + kc * 32);
        LDMX4(alo, aLo + kc * 32);
#pragma unroll
        for (int nt = 0; nt < 8; nt++) {
            uint32_t bb = sbase + SB_HI + nt * 8 * 144 + bRowOff + kc * 32;
            uint32_t bhi[2], blo[2];
            LDMX2(bhi, bb);
            LDMX2(blo, bb + (SB_LO - SB_HI));
            MMA16816(acc[nt], ahi, bhi);
            MMA16816(acc[nt], ahi, blo);
            MMA16816(acc[nt], alo, bhi);
        }
    }

    // epilogue: lane holds rows (r0+lane/4, +8), cols nt*8 + (lane&3)*2 (+1)
    int row0 = r0 + (lane >> 2);
    int n0 = nb + row0, n1 = n0 + 8;
#pragma unroll
    for (int nt = 0; nt < 8; nt++) {
        int col = nt * 8 + (lane & 3) * 2;
        float2 bb2 = *(const float2*)(bias + col);
        float2 o0, o1;
        o0.x = acc[nt][0] + bb2.x; o0.y = acc[nt][1] + bb2.y;
        o1.x = acc[nt][2] + bb2.x; o1.y = acc[nt][3] + bb2.y;
        *(float2*)(out + (size_t)n0 * 64 + col) = o0;
        *(float2*)(out + (size_t)n1 * 64 + col) = o1;
        if (n0 < Nv) {
            float2 s0; s0.x = acc[nt][0]; s0.y = acc[nt][1];
            *(float2*)(g_xlS + n0 * 64 + col) = s0;
        }
        if (n1 < Nv) {
            float2 s1; s1.x = acc[nt][2]; s1.y = acc[nt][3];
            *(float2*)(g_xlS + n1 * 64 + col) = s1;
        }
    }
    if (nb < Nv) {
        float ps0 = 0.f, pd0 = 0.f, ps1 = 0.f, pd1 = 0.f;
#pragma unroll
        for (int nt = 0; nt < 8; nt++) {
            int col = nt * 8 + (lane & 3) * 2;
            float2 a2 = *(const float2*)(attS + col);
            float2 d2 = *(const float2*)(attD + col);
            ps0 += acc[nt][0] * a2.x + acc[nt][1] * a2.y;
            pd0 += acc[nt][0] * d2.x + acc[nt][1] * d2.y;
            ps1 += acc[nt][2] * a2.x + acc[nt][3] * a2.y;
            pd1 += acc[nt][2] * d2.x + acc[nt][3] * d2.y;
        }
#pragma unroll
        for (int o = 1; o <= 2; o <<= 1) {
            ps0 += __shfl_xor_sync(0xffffffffu, ps0, o);
            pd0 += __shfl_xor_sync(0xffffffffu, pd0, o);
            ps1 += __shfl_xor_sync(0xffffffffu, ps1, o);
            pd1 += __shfl_xor_sync(0xffffffffu, pd1, o);
        }
        if ((lane & 3) == 0) {
            if (n0 < Nv) { g_aS[n0] = ps0; g_aD[n0] = pd0; }
            if (n1 < Nv) { g_aS[n1] = ps1; g_aD[n1] = pd1; }
        }
    }
}

// ------- bucket scatter (replaces hist+scan+scatter) + ea sum -------
__global__ void k_scatter(const int* __restrict__ ei, const float* __restrict__ ea) {
    int e = blockIdx.x * 256 + threadIdx.x;          // exact: Ev = 625*256
    int d = ei[Ev + e];
    int s = ei[e];
    float v = ea[e];
    int pos = atomicAdd(&g_bcnt[d], 1);
    int idx = d * CAP + pos;
    g_bsrc[idx] = s;
    g_bval[idx] = v;
    g_bedge[idx] = e;
    // block-reduce ea, one atomicAdd per block into g_bcnt[Nv] (as float)
    float t = v;
#pragma unroll
    for (int o = 16; o; o >>= 1) t += __shfl_xor_sync(0xffffffffu, t, o);
    __shared__ float sh[8];
    if ((threadIdx.x & 31) == 0) sh[threadIdx.x >> 5] = t;
    __syncthreads();
    if (threadIdx.x < 8) {
        float w = sh[threadIdx.x];
#pragma unroll
        for (int o = 4; o; o >>= 1) w += __shfl_xor_sync(0xffu, w, o);
        if (threadIdx.x == 0) atomicAdd((float*)g_bcnt + Nv, w);
    }
}

// ------- per-destination softmax + aggregation: one warp per dst -------
__global__ void __launch_bounds__(256) k_dst(const float* __restrict__ W_edge,
                                             const float* __restrict__ attE,
                                             const float* __restrict__ bias,
                                             float* __restrict__ out) {
    int wIdx = threadIdx.x >> 5;
    int d = blockIdx.x * 8 + wIdx;
    int lane = threadIdx.x & 31;
    if (d >= Nv) return;
    // per-warp c = sum W_edge*att_edge
    float cv = W_edge[lane] * attE[lane] + W_edge[lane + 32] * attE[lane + 32];
#pragma unroll
    for (int o = 16; o; o >>= 1) cv += __shfl_xor_sync(0xffffffffu, cv, o);
    float meanC = ((const float*)g_bcnt)[Nv] * (1.f / (float)Ev) * cv;

    int cnt = g_bcnt[d];
    int base = d * CAP;
    float aDd = g_aD[d];
    float pSelf;
    {
        float xv = g_aS[d] + aDd + meanC;
        xv = xv > 0.f ? xv : 0.2f * xv;
        pSelf = __expf(xv);
    }
    __shared__ float sP[8][32];
    __shared__ int   sS[8][32];
    float a0x = 0.f, a0y = 0.f, a1x = 0.f, a1y = 0.f;
    float a2x = 0.f, a2y = 0.f, a3x = 0.f, a3y = 0.f;
    float psum = 0.f;
    for (int b0 = 0; b0 < cnt; b0 += 32) {
        int m = cnt - b0; if (m > 32) m = 32;
        if (lane < m) {
            int idx = base + b0 + lane;
            int s = g_bsrc[idx];
            float xv = g_aS[s] + aDd + g_bval[idx] * cv;
            xv = xv > 0.f ? xv : 0.2f * xv;
            float p = __expf(xv);
            psum += p;
            sP[wIdx][lane] = p;
            sS[wIdx][lane] = s;
        }
        __syncwarp();
        int j = 0;
        for (; j + 4 <= m; j += 4) {
            float p0 = sP[wIdx][j],     p1 = sP[wIdx][j + 1];
            float p2 = sP[wIdx][j + 2], p3 = sP[wIdx][j + 3];
            int   q0 = sS[wIdx][j],     q1 = sS[wIdx][j + 1];
            int   q2 = sS[wIdx][j + 2], q3 = sS[wIdx][j + 3];
            float2 v0 = *(const float2*)(g_xlS + q0 * 64 + lane * 2);
            float2 v1 = *(const float2*)(g_xlS + q1 * 64 + lane * 2);
            float2 v2 = *(const float2*)(g_xlS + q2 * 64 + lane * 2);
            float2 v3 = *(const float2*)(g_xlS + q3 * 64 + lane * 2);
            a0x += p0 * v0.x; a0y += p0 * v0.y;
            a1x += p1 * v1.x; a1y += p1 * v1.y;
            a2x += p2 * v2.x; a2y += p2 * v2.y;
            a3x += p3 * v3.x; a3y += p3 * v3.y;
        }
        for (; j < m; j++) {
            float p0 = sP[wIdx][j];
            int   q0 = sS[wIdx][j];
            float2 v0 = *(const float2*)(g_xlS + q0 * 64 + lane * 2);
            a0x += p0 * v0.x; a0y += p0 * v0.y;
        }
        __syncwarp();
    }
    float accx = (a0x + a1x) + (a2x + a3x);
    float accy = (a0y + a1y) + (a2y + a3y);
#pragma unroll
    for (int o = 16; o; o >>= 1) psum += __shfl_xor_sync(0xffffffffu, psum, o);
    float denom = (float)Bv * psum + pSelf;
    float rd = 1.f / (denom + 1e-16f);
    float2 xs = *(const float2*)(g_xlS + d * 64 + lane * 2);
    float2 bb = *(const float2*)(bias + lane * 2);
    float2 o2;
    o2.x = ((float)Bv * accx + pSelf * xs.x) * rd + bb.x;
    o2.y = ((float)Bv * accy + pSelf * xs.y) * rd + bb.y;
    *(float2*)(out + (long long)d * 64 + lane * 2) = o2;
    if (lane == 0) g_selfNorm[d] = pSelf * rd;
    // normalized alpha per unique edge (recompute p; inputs L1-hot)
    for (int i = lane; i < cnt; i += 32) {
        int idx = base + i;
        int s = g_bsrc[idx];
        float xv = g_aS[s] + aDd + g_bval[idx] * cv;
        xv = xv > 0.f ? xv : 0.2f * xv;
        g_alphaP[g_bedge[idx]] = __expf(xv) * rd;
    }
}

// ------- tuple tail part 1: src/dst rows, float4 -------
__global__ void k_tail_sd(const int* __restrict__ ei, float* __restrict__ outTail) {
    int i = (blockIdx.x * 256 + threadIdx.x) * 4;
    if (i >= 2 * ETOTv) return;
    float4 v;
    if (i < ETOTv) {
        if (i < BEv) {
            int e = i - (i / Ev) * Ev;
            v.x = (float)ei[e]; v.y = (float)ei[e + 1];
            v.z = (float)ei[e + 2]; v.w = (float)ei[e + 3];
        } else {
            float b0 = (float)(i - BEv);
            v.x = b0; v.y = b0 + 1.f; v.z = b0 + 2.f; v.w = b0 + 3.f;
        }
    } else {
        int k = i - ETOTv;
        if (k < BEv) {
            int e = k - (k / Ev) * Ev;
            v.x = (float)ei[Ev + e]; v.y = (float)ei[Ev + e + 1];
            v.z = (float)ei[Ev + e + 2]; v.w = (float)ei[Ev + e + 3];
        } else {
            float b0 = (float)(k - BEv);
            v.x = b0; v.y = b0 + 1.f; v.z = b0 + 2.f; v.w = b0 + 3.f;
        }
    }
    *(float4*)(outTail + i) = v;
}

// ------- tuple tail part 2: alpha, float4 -------
__global__ void k_tail_alpha(float* __restrict__ outA, int totalA) {
    int i = (blockIdx.x * 256 + threadIdx.x) * 4;
    if (i >= totalA) return;
    float4 v;
    if (i < BEv) {
        int e = i - (i / Ev) * Ev;
        v = *(const float4*)(g_alphaP + e);
    } else {
        int d = i - BEv;
        if (d + 3 < Nv) {
            v.x = g_selfNorm[d]; v.y = g_selfNorm[d + 1];
            v.z = g_selfNorm[d + 2]; v.w = g_selfNorm[d + 3];
        } else {
            v.x = (d     < Nv) ? g_selfNorm[d]     : 1.0f;
            v.y = (d + 1 < Nv) ? g_selfNorm[d + 1] : 1.0f;
            v.z = (d + 2 < Nv) ? g_selfNorm[d + 2] : 1.0f;
            v.w = (d + 3 < Nv) ? g_selfNorm[d + 3] : 1.0f;
        }
    }
    *(float4*)(outA + i) = v;
}

// ---------------- launch ----------------
extern "C" void kernel_launch(void* const* d_in, const int* in_sizes, int n_in,
                              void* d_out, int out_size) {
    const float* data   = (const float*)d_in[0];
    const int*   ei     = (const int*)  d_in[1];
    const float* ea     = (const float*)d_in[2];
    const float* W      = (const float*)d_in[3];
    const float* W_edge = (const float*)d_in[4];
    const float* attS   = (const float*)d_in[5];
    const float* attD   = (const float*)d_in[6];
    const float* attE   = (const float*)d_in[7];
    const float* bias   = (const float*)d_in[8];
    float* out = (float*)d_out;

    static cudaStream_t sB = nullptr, sC = nullptr;
    static cudaEvent_t eFork = nullptr, eB = nullptr, eC = nullptr;
    if (!sB) {
        cudaStreamCreateWithFlags(&sB, cudaStreamNonBlocking);
        cudaStreamCreateWithFlags(&sC, cudaStreamNonBlocking);
        cudaEventCreateWithFlags(&eFork, cudaEventDisableTiming);
        cudaEventCreateWithFlags(&eB, cudaEventDisableTiming);
        cudaEventCreateWithFlags(&eC, cudaEventDisableTiming);
        cudaFuncSetAttribute(k_gemm, cudaFuncAttributeMaxDynamicSharedMemorySize, SM_TOT);
    }

    void* bcntAddr = nullptr;
    cudaGetSymbolAddress(&bcntAddr, g_bcnt);

    cudaEventRecord(eFork, 0);
    cudaStreamWaitEvent(sB, eFork, 0);
    cudaStreamWaitEvent(sC, eFork, 0);

    // side chain: bucket CSR build (no hist/scan)
    cudaMemsetAsync(bcntAddr, 0, (Nv + 2) * sizeof(int), sB);
    k_scatter<<<NPART, 256, 0, sB>>>(ei, ea);
    cudaEventRecord(eB, sB);

    // tail src/dst rows (independent)
    if (out_size > OUT_MAIN) {
        int n4 = (2 * ETOTv) / 4;
        k_tail_sd<<<(n4 + 255) / 256, 256, 0, sC>>>(ei, out + OUT_MAIN);
    }
    cudaEventRecord(eC, sC);

    // main: W image + tensor GEMM
    k_wconv<<<1, 256>>>(W);
    k_gemm<<<BNv / 128, 256, SM_TOT>>>(data, bias, attS, attD, out);

    cudaStreamWaitEvent(0, eB, 0);
    k_dst<<<(Nv + 7) / 8, 256>>>(W_edge, attE, bias, out);

    if (out_size > OUT_MAIN) {
        int totalA = out_size - OUT_MAIN - 2 * ETOTv;
        if (totalA > 0) {
            int n4 = (totalA + 3) / 4;
            k_tail_alpha<<<(n4 + 255) / 256, 256>>>(out + OUT_MAIN + 2 * ETOTv, totalA);
        }
    }

    cudaStreamWaitEvent(0, eC, 0);
}

// round 9
// speedup vs baseline: 1.8238x; 1.0970x over previous
#include <cuda_runtime.h>
#include <cuda_bf16.h>
#include <cstdint>

#define Bv   16
#define Nv   5000
#define Ev   160000
#define BNv  80000
#define BEv  2560000
#define ETOTv 2640000
#define OUT_MAIN 5120000   // BNv * 64
#define NPART 625          // Ev / 256
#define CAP  128           // bucket capacity per destination
#define HEADBLKS 40        // blocks covering nodes < Nv (40*128 = 5120)

// ---------------- scratch (static __device__, no allocs) ----------------
__device__ float g_xlS[Nv * 64];
__device__ float g_aS[Nv];
__device__ float g_aD[Nv];
__device__ int   g_bcnt[Nv + 2];     // [Nv] reused as float sum(ea)
__device__ int   g_bsrc[Nv * CAP];
__device__ int   g_bedge[Nv * CAP];
__device__ float g_bval[Nv * CAP];   // raw ea per slot
__device__ float g_alphaP[Ev];       // normalized alpha per unique edge
__device__ float g_selfNorm[Nv];
__device__ uint4 g_Wimg[1152];       // 18432B: W_hi [64][72]bf16 | W_lo [64][72]bf16

// ---------------- helpers ----------------
__device__ __forceinline__ uint32_t smem_to_u32(const void* p) {
    uint32_t a;
    asm("{ .reg .u64 t; cvta.to.shared.u64 t, %1; cvt.u32.u64 %0, t; }" : "=r"(a) : "l"(p));
    return a;
}
__device__ __forceinline__ uint32_t pack_hi(float2 v) {
    __nv_bfloat162 h = __float22bfloat162_rn(v);
    return *(uint32_t*)&h;
}
__device__ __forceinline__ uint32_t pack_lo(float2 v, uint32_t hi) {
    __nv_bfloat162 h = *(__nv_bfloat162*)&hi;
    float2 hf = __bfloat1622float2(h);
    float2 r; r.x = v.x - hf.x; r.y = v.y - hf.y;
    __nv_bfloat162 l = __float22bfloat162_rn(r);
    return *(uint32_t*)&l;
}
#define LDMX2(r, a) \
    asm volatile("ldmatrix.sync.aligned.m8n8.x2.shared.b16 {%0,%1}, [%2];" \
        : "=r"((r)[0]), "=r"((r)[1]) : "r"(a))
#define MMA16816(c, a, b) \
    asm volatile("mma.sync.aligned.m16n8k16.row.col.f32.bf16.bf16.f32 " \
        "{%0,%1,%2,%3}, {%4,%5,%6,%7}, {%8,%9}, {%0,%1,%2,%3};" \
        : "+f"((c)[0]), "+f"((c)[1]), "+f"((c)[2]), "+f"((c)[3]) \
        : "r"((a)[0]), "r"((a)[1]), "r"((a)[2]), "r"((a)[3]), "r"((b)[0]), "r"((b)[1]))

// ---------------- W -> bf16 hi/lo image [64 rows][72 bf16] ----------------
__global__ void k_wconv(const float* __restrict__ W) {
    int p = blockIdx.x * 256 + threadIdx.x;          // 8 blocks x 256 = 2048
    char* img = (char*)g_Wimg;
    int c = p >> 5, cp = p & 31;
    float2 v = *(const float2*)(W + c * 64 + cp * 2);
    uint32_t hu = pack_hi(v);
    uint32_t lu = pack_lo(v, hu);
    *(unsigned*)(img + c * 144 + cp * 4) = hu;
    *(unsigned*)(img + 9216 + c * 144 + cp * 4) = lu;
}

// ---- tensor GEMM: A direct-to-register, B ldmatrix, batched loads ----
__global__ void __launch_bounds__(256, 2) k_gemm(const float* __restrict__ x,
                                                 const float* __restrict__ bias,
                                                 const float* __restrict__ attS,
                                                 const float* __restrict__ attD,
                                                 float* __restrict__ out,
                                                 int blockOff) {
    __shared__ char smB[18432];
    int tid = threadIdx.x, wid = tid >> 5, lane = tid & 31;
    int nb = (blockIdx.x + blockOff) * 128;

    // stage B image (hi | lo)
    {
        uint4* dst = (uint4*)smB;
#pragma unroll
        for (int i = 0; i < 5; i++) {
            int j = tid + i * 256;
            if (j < 1152) dst[j] = g_Wimg[j];
        }
    }

    // A: direct global loads -> 16 independent LDG.64, then convert
    int r0 = wid * 16 + (lane >> 2);
    const float* xr = x + (size_t)(nb + r0) * 64 + (lane & 3) * 2;
    float2 v[4][4];
#pragma unroll
    for (int kc = 0; kc < 4; kc++) {
        v[kc][0] = *(const float2*)(xr + kc * 16);            // (r, k)
        v[kc][1] = *(const float2*)(xr + 8 * 64 + kc * 16);   // (r+8, k)
        v[kc][2] = *(const float2*)(xr + kc * 16 + 8);        // (r, k+8)
        v[kc][3] = *(const float2*)(xr + 8 * 64 + kc * 16 + 8); // (r+8, k+8)
    }
    uint32_t ahi[4][4], alo[4][4];
#pragma unroll
    for (int kc = 0; kc < 4; kc++)
#pragma unroll
        for (int j = 0; j < 4; j++) {
            ahi[kc][j] = pack_hi(v[kc][j]);
            alo[kc][j] = pack_lo(v[kc][j], ahi[kc][j]);
        }
    __syncthreads();

    uint32_t sb = smem_to_u32(smB);
    uint32_t bOff = (lane & 7) * 144 + ((lane >> 3) & 1) * 16;

    float acc[8][4];
#pragma unroll
    for (int nt = 0; nt < 8; nt++)
#pragma unroll
        for (int j = 0; j < 4; j++) acc[nt][j] = 0.f;

#pragma unroll
    for (int kc = 0; kc < 4; kc++) {
        uint32_t bh[8][2], bl[8][2];
#pragma unroll
        for (int nt = 0; nt < 8; nt++) {
            uint32_t ba = sb + nt * 1152 + bOff + kc * 32;
            LDMX2(bh[nt], ba);
            LDMX2(bl[nt], ba + 9216);
        }
#pragma unroll
        for (int nt = 0; nt < 8; nt++) {
            MMA16816(acc[nt], ahi[kc], bh[nt]);
            MMA16816(acc[nt], ahi[kc], bl[nt]);
            MMA16816(acc[nt], alo[kc], bh[nt]);
        }
    }

    // epilogue: thread holds rows r0, r0+8; cols nt*8 + (lane&3)*2
    int n0 = nb + r0, n1 = n0 + 8;
#pragma unroll
    for (int nt = 0; nt < 8; nt++) {
        int col = nt * 8 + (lane & 3) * 2;
        float2 bb2 = *(const float2*)(bias + col);
        float2 o0, o1;
        o0.x = acc[nt][0] + bb2.x; o0.y = acc[nt][1] + bb2.y;
        o1.x = acc[nt][2] + bb2.x; o1.y = acc[nt][3] + bb2.y;
        *(float2*)(out + (size_t)n0 * 64 + col) = o0;
        *(float2*)(out + (size_t)n1 * 64 + col) = o1;
        if (n0 < Nv) {
            float2 s0; s0.x = acc[nt][0]; s0.y = acc[nt][1];
            *(float2*)(g_xlS + n0 * 64 + col) = s0;
        }
        if (n1 < Nv) {
            float2 s1; s1.x = acc[nt][2]; s1.y = acc[nt][3];
            *(float2*)(g_xlS + n1 * 64 + col) = s1;
        }
    }
    if (nb < Nv) {
        float ps0 = 0.f, pd0 = 0.f, ps1 = 0.f, pd1 = 0.f;
#pragma unroll
        for (int nt = 0; nt < 8; nt++) {
            int col = nt * 8 + (lane & 3) * 2;
            float2 a2 = *(const float2*)(attS + col);
            float2 d2 = *(const float2*)(attD + col);
            ps0 += acc[nt][0] * a2.x + acc[nt][1] * a2.y;
            pd0 += acc[nt][0] * d2.x + acc[nt][1] * d2.y;
            ps1 += acc[nt][2] * a2.x + acc[nt][3] * a2.y;
            pd1 += acc[nt][2] * d2.x + acc[nt][3] * d2.y;
        }
#pragma unroll
        for (int o = 1; o <= 2; o <<= 1) {
            ps0 += __shfl_xor_sync(0xffffffffu, ps0, o);
            pd0 += __shfl_xor_sync(0xffffffffu, pd0, o);
            ps1 += __shfl_xor_sync(0xffffffffu, ps1, o);
            pd1 += __shfl_xor_sync(0xffffffffu, pd1, o);
        }
        if ((lane & 3) == 0) {
            if (n0 < Nv) { g_aS[n0] = ps0; g_aD[n0] = pd0; }
            if (n1 < Nv) { g_aS[n1] = ps1; g_aD[n1] = pd1; }
        }
    }
}

// ------- bucket scatter + ea sum -------
__global__ void k_scatter(const int* __restrict__ ei, const float* __restrict__ ea) {
    int e = blockIdx.x * 256 + threadIdx.x;
    int d = ei[Ev + e];
    int s = ei[e];
    float v = ea[e];
    int pos = atomicAdd(&g_bcnt[d], 1);
    int idx = d * CAP + pos;
    g_bsrc[idx] = s;
    g_bval[idx] = v;
    g_bedge[idx] = e;
    float t = v;
#pragma unroll
    for (int o = 16; o; o >>= 1) t += __shfl_xor_sync(0xffffffffu, t, o);
    __shared__ float sh[8];
    if ((threadIdx.x & 31) == 0) sh[threadIdx.x >> 5] = t;
    __syncthreads();
    if (threadIdx.x < 8) {
        float w = sh[threadIdx.x];
#pragma unroll
        for (int o = 4; o; o >>= 1) w += __shfl_xor_sync(0xffu, w, o);
        if (threadIdx.x == 0) atomicAdd((float*)g_bcnt + Nv, w);
    }
}

// ------- per-destination softmax + aggregation: one warp per dst -------
__global__ void __launch_bounds__(256) k_dst(const float* __restrict__ W_edge,
                                             const float* __restrict__ attE,
                                             const float* __restrict__ bias,
                                             float* __restrict__ out) {
    int wIdx = threadIdx.x >> 5;
    int d = blockIdx.x * 8 + wIdx;
    int lane = threadIdx.x & 31;
    if (d >= Nv) return;
    float cv = W_edge[lane] * attE[lane] + W_edge[lane + 32] * attE[lane + 32];
#pragma unroll
    for (int o = 16; o; o >>= 1) cv += __shfl_xor_sync(0xffffffffu, cv, o);
    float meanC = ((const float*)g_bcnt)[Nv] * (1.f / (float)Ev) * cv;

    int cnt = g_bcnt[d];
    int base = d * CAP;
    float aDd = g_aD[d];
    float pSelf;
    {
        float xv = g_aS[d] + aDd + meanC;
        xv = xv > 0.f ? xv : 0.2f * xv;
        pSelf = __expf(xv);
    }
    __shared__ float sP[8][32];
    __shared__ int   sS[8][32];
    float a0x = 0.f, a0y = 0.f, a1x = 0.f, a1y = 0.f;
    float a2x = 0.f, a2y = 0.f, a3x = 0.f, a3y = 0.f;
    float psum = 0.f;
    for (int b0 = 0; b0 < cnt; b0 += 32) {
        int m = cnt - b0; if (m > 32) m = 32;
        if (lane < m) {
            int idx = base + b0 + lane;
            int s = g_bsrc[idx];
            float xv = g_aS[s] + aDd + g_bval[idx] * cv;
            xv = xv > 0.f ? xv : 0.2f * xv;
            float p = __expf(xv);
            psum += p;
            sP[wIdx][lane] = p;
            sS[wIdx][lane] = s;
        }
        __syncwarp();
        int j = 0;
        for (; j + 4 <= m; j += 4) {
            float p0 = sP[wIdx][j],     p1 = sP[wIdx][j + 1];
            float p2 = sP[wIdx][j + 2], p3 = sP[wIdx][j + 3];
            int   q0 = sS[wIdx][j],     q1 = sS[wIdx][j + 1];
            int   q2 = sS[wIdx][j + 2], q3 = sS[wIdx][j + 3];
            float2 v0 = *(const float2*)(g_xlS + q0 * 64 + lane * 2);
            float2 v1 = *(const float2*)(g_xlS + q1 * 64 + lane * 2);
            float2 v2 = *(const float2*)(g_xlS + q2 * 64 + lane * 2);
            float2 v3 = *(const float2*)(g_xlS + q3 * 64 + lane * 2);
            a0x += p0 * v0.x; a0y += p0 * v0.y;
            a1x += p1 * v1.x; a1y += p1 * v1.y;
            a2x += p2 * v2.x; a2y += p2 * v2.y;
            a3x += p3 * v3.x; a3y += p3 * v3.y;
        }
        for (; j < m; j++) {
            float p0 = sP[wIdx][j];
            int   q0 = sS[wIdx][j];
            float2 v0 = *(const float2*)(g_xlS + q0 * 64 + lane * 2);
            a0x += p0 * v0.x; a0y += p0 * v0.y;
        }
        __syncwarp();
    }
    float accx = (a0x + a1x) + (a2x + a3x);
    float accy = (a0y + a1y) + (a2y + a3y);
#pragma unroll
    for (int o = 16; o; o >>= 1) psum += __shfl_xor_sync(0xffffffffu, psum, o);
    float denom = (float)Bv * psum + pSelf;
    float rd = 1.f / (denom + 1e-16f);
    float2 xs = *(const float2*)(g_xlS + d * 64 + lane * 2);
    float2 bb = *(const float2*)(bias + lane * 2);
    float2 o2;
    o2.x = ((float)Bv * accx + pSelf * xs.x) * rd + bb.x;
    o2.y = ((float)Bv * accy + pSelf * xs.y) * rd + bb.y;
    *(float2*)(out + (long long)d * 64 + lane * 2) = o2;
    if (lane == 0) g_selfNorm[d] = pSelf * rd;
    for (int i = lane; i < cnt; i += 32) {
        int idx = base + i;
        int s = g_bsrc[idx];
        float xv = g_aS[s] + aDd + g_bval[idx] * cv;
        xv = xv > 0.f ? xv : 0.2f * xv;
        g_alphaP[g_bedge[idx]] = __expf(xv) * rd;
    }
}

// ------- tuple tail part 1: src/dst rows, float4 -------
__global__ void k_tail_sd(const int* __restrict__ ei, float* __restrict__ outTail) {
    int i = (blockIdx.x * 256 + threadIdx.x) * 4;
    if (i >= 2 * ETOTv) return;
    float4 v;
    if (i < ETOTv) {
        if (i < BEv) {
            int e = i - (i / Ev) * Ev;
            v.x = (float)ei[e]; v.y = (float)ei[e + 1];
            v.z = (float)ei[e + 2]; v.w = (float)ei[e + 3];
        } else {
            float b0 = (float)(i - BEv);
            v.x = b0; v.y = b0 + 1.f; v.z = b0 + 2.f; v.w = b0 + 3.f;
        }
    } else {
        int k = i - ETOTv;
        if (k < BEv) {
            int e = k - (k / Ev) * Ev;
            v.x = (float)ei[Ev + e]; v.y = (float)ei[Ev + e + 1];
            v.z = (float)ei[Ev + e + 2]; v.w = (float)ei[Ev + e + 3];
        } else {
            float b0 = (float)(k - BEv);
            v.x = b0; v.y = b0 + 1.f; v.z = b0 + 2.f; v.w = b0 + 3.f;
        }
    }
    *(float4*)(outTail + i) = v;
}

// ------- tuple tail part 2: alpha, float4 -------
__global__ void k_tail_alpha(float* __restrict__ outA, int totalA) {
    int i = (blockIdx.x * 256 + threadIdx.x) * 4;
    if (i >= totalA) return;
    float4 v;
    if (i < BEv) {
        int e = i - (i / Ev) * Ev;
        v = *(const float4*)(g_alphaP + e);
    } else {
        int d = i - BEv;
        if (d + 3 < Nv) {
            v.x = g_selfNorm[d]; v.y = g_selfNorm[d + 1];
            v.z = g_selfNorm[d + 2]; v.w = g_selfNorm[d + 3];
        } else {
            v.x = (d     < Nv) ? g_selfNorm[d]     : 1.0f;
            v.y = (d + 1 < Nv) ? g_selfNorm[d + 1] : 1.0f;
            v.z = (d + 2 < Nv) ? g_selfNorm[d + 2] : 1.0f;
            v.w = (d + 3 < Nv) ? g_selfNorm[d + 3] : 1.0f;
        }
    }
    *(float4*)(outA + i) = v;
}

// ---------------- launch ----------------
extern "C" void kernel_launch(void* const* d_in, const int* in_sizes, int n_in,
                              void* d_out, int out_size) {
    const float* data   = (const float*)d_in[0];
    const int*   ei     = (const int*)  d_in[1];
    const float* ea     = (const float*)d_in[2];
    const float* W      = (const float*)d_in[3];
    const float* W_edge = (const float*)d_in[4];
    const float* attS   = (const float*)d_in[5];
    const float* attD   = (const float*)d_in[6];
    const float* attE   = (const float*)d_in[7];
    const float* bias   = (const float*)d_in[8];
    float* out = (float*)d_out;

    static cudaStream_t sB = nullptr, sC = nullptr, sD = nullptr;
    static cudaEvent_t eFork = nullptr, eB = nullptr, eC = nullptr, eW = nullptr, eD = nullptr;
    if (!sB) {
        cudaStreamCreateWithFlags(&sB, cudaStreamNonBlocking);
        cudaStreamCreateWithFlags(&sC, cudaStreamNonBlocking);
        cudaStreamCreateWithFlags(&sD, cudaStreamNonBlocking);
        cudaEventCreateWithFlags(&eFork, cudaEventDisableTiming);
        cudaEventCreateWithFlags(&eB, cudaEventDisableTiming);
        cudaEventCreateWithFlags(&eC, cudaEventDisableTiming);
        cudaEventCreateWithFlags(&eW, cudaEventDisableTiming);
        cudaEventCreateWithFlags(&eD, cudaEventDisableTiming);
    }

    void* bcntAddr = nullptr;
    cudaGetSymbolAddress(&bcntAddr, g_bcnt);

    cudaEventRecord(eFork, 0);
    cudaStreamWaitEvent(sB, eFork, 0);
    cudaStreamWaitEvent(sC, eFork, 0);

    // side chain: bucket CSR build
    cudaMemsetAsync(bcntAddr, 0, (Nv + 2) * sizeof(int), sB);
    k_scatter<<<NPART, 256, 0, sB>>>(ei, ea);
    cudaEventRecord(eB, sB);

    // tail src/dst rows (independent)
    if (out_size > OUT_MAIN) {
        int n4 = (2 * ETOTv) / 4;
        k_tail_sd<<<(n4 + 255) / 256, 256, 0, sC>>>(ei, out + OUT_MAIN);
    }
    cudaEventRecord(eC, sC);

    // W image, then head (main) and rest (sD) CONCURRENTLY
    k_wconv<<<8, 256>>>(W);
    cudaEventRecord(eW, 0);
    cudaStreamWaitEvent(sD, eW, 0);
    k_gemm<<<BNv / 128 - HEADBLKS, 256, 0, sD>>>(data, bias, attS, attD, out, HEADBLKS);
    cudaEventRecord(eD, sD);
    k_gemm<<<HEADBLKS, 256>>>(data, bias, attS, attD, out, 0);

    // main: wait CSR, then softmax/aggregate (overlaps gemm_rest), alpha tail
    cudaStreamWaitEvent(0, eB, 0);
    k_dst<<<(Nv + 7) / 8, 256>>>(W_edge, attE, bias, out);

    if (out_size > OUT_MAIN) {
        int totalA = out_size - OUT_MAIN - 2 * ETOTv;
        if (totalA > 0) {
            int n4 = (totalA + 3) / 4;
            k_tail_alpha<<<(n4 + 255) / 256, 256>>>(out + OUT_MAIN + 2 * ETOTv, totalA);
        }
    }

    cudaStreamWaitEvent(0, eC, 0);
    cudaStreamWaitEvent(0, eD, 0);
}

// round 11
// speedup vs baseline: 1.9005x; 1.0421x over previous
#include <cuda_runtime.h>
#include <cuda_bf16.h>
#include <cstdint>

#define Bv   16
#define Nv   5000
#define Ev   160000
#define BNv  80000
#define BEv  2560000
#define ETOTv 2640000
#define OUT_MAIN 5120000   // BNv * 64
#define NPART 625          // Ev / 256
#define CAP  128           // bucket capacity per destination
#define HEADBLKS 40        // blocks covering nodes < Nv (40*128 = 5120)

// ---------------- scratch (static __device__, no allocs) ----------------
__device__ float g_xlS[Nv * 64];
__device__ float g_aS[Nv];
__device__ float g_aD[Nv];
__device__ int   g_bcnt[Nv + 2];     // [Nv] reused as float sum(ea)
__device__ int   g_bsrc[Nv * CAP];
__device__ int   g_bedge[Nv * CAP];
__device__ float g_bval[Nv * CAP];   // raw ea per slot
__device__ float g_alphaC[Nv * CAP]; // unnormalized p, CSR-slot order
__device__ float g_alphaP[Ev];       // normalized alpha per unique edge
__device__ float g_selfNorm[Nv];
__device__ uint4 g_Wimg[1152];       // 18432B: W_hi [64][72]bf16 | W_lo [64][72]bf16

// ---------------- helpers ----------------
__device__ __forceinline__ uint32_t smem_to_u32(const void* p) {
    uint32_t a;
    asm("{ .reg .u64 t; cvta.to.shared.u64 t, %1; cvt.u32.u64 %0, t; }" : "=r"(a) : "l"(p));
    return a;
}
__device__ __forceinline__ uint32_t pack_hi(float2 v) {
    __nv_bfloat162 h = __float22bfloat162_rn(v);
    return *(uint32_t*)&h;
}
__device__ __forceinline__ uint32_t pack_lo(float2 v, uint32_t hi) {
    __nv_bfloat162 h = *(__nv_bfloat162*)&hi;
    float2 hf = __bfloat1622float2(h);
    float2 r; r.x = v.x - hf.x; r.y = v.y - hf.y;
    __nv_bfloat162 l = __float22bfloat162_rn(r);
    return *(uint32_t*)&l;
}
#define LDMX2(r, a) \
    asm volatile("ldmatrix.sync.aligned.m8n8.x2.shared.b16 {%0,%1}, [%2];" \
        : "=r"((r)[0]), "=r"((r)[1]) : "r"(a))
#define MMA16816(c, a, b) \
    asm volatile("mma.sync.aligned.m16n8k16.row.col.f32.bf16.bf16.f32 " \
        "{%0,%1,%2,%3}, {%4,%5,%6,%7}, {%8,%9}, {%0,%1,%2,%3};" \
        : "+f"((c)[0]), "+f"((c)[1]), "+f"((c)[2]), "+f"((c)[3]) \
        : "r"((a)[0]), "r"((a)[1]), "r"((a)[2]), "r"((a)[3]), "r"((b)[0]), "r"((b)[1]))

// ---------------- W -> bf16 hi/lo image [64 rows][72 bf16] ----------------
__global__ void k_wconv(const float* __restrict__ W) {
    int p = blockIdx.x * 256 + threadIdx.x;          // 8 blocks x 256 = 2048
    char* img = (char*)g_Wimg;
    int c = p >> 5, cp = p & 31;
    float2 v = *(const float2*)(W + c * 64 + cp * 2);
    uint32_t hu = pack_hi(v);
    uint32_t lu = pack_lo(v, hu);
    *(unsigned*)(img + c * 144 + cp * 4) = hu;
    *(unsigned*)(img + 9216 + c * 144 + cp * 4) = lu;
}

// ---- tensor GEMM: A direct-to-register, B ldmatrix, batched loads ----
__global__ void __launch_bounds__(256, 2) k_gemm(const float* __restrict__ x,
                                                 const float* __restrict__ bias,
                                                 const float* __restrict__ attS,
                                                 const float* __restrict__ attD,
                                                 float* __restrict__ out,
                                                 int blockOff) {
    __shared__ char smB[18432];
    int tid = threadIdx.x, wid = tid >> 5, lane = tid & 31;
    int nb = (blockIdx.x + blockOff) * 128;

    {
        uint4* dst = (uint4*)smB;
#pragma unroll
        for (int i = 0; i < 5; i++) {
            int j = tid + i * 256;
            if (j < 1152) dst[j] = g_Wimg[j];
        }
    }

    int r0 = wid * 16 + (lane >> 2);
    const float* xr = x + (size_t)(nb + r0) * 64 + (lane & 3) * 2;
    float2 v[4][4];
#pragma unroll
    for (int kc = 0; kc < 4; kc++) {
        v[kc][0] = *(const float2*)(xr + kc * 16);
        v[kc][1] = *(const float2*)(xr + 8 * 64 + kc * 16);
        v[kc][2] = *(const float2*)(xr + kc * 16 + 8);
        v[kc][3] = *(const float2*)(xr + 8 * 64 + kc * 16 + 8);
    }
    uint32_t ahi[4][4], alo[4][4];
#pragma unroll
    for (int kc = 0; kc < 4; kc++)
#pragma unroll
        for (int j = 0; j < 4; j++) {
            ahi[kc][j] = pack_hi(v[kc][j]);
            alo[kc][j] = pack_lo(v[kc][j], ahi[kc][j]);
        }
    __syncthreads();

    uint32_t sb = smem_to_u32(smB);
    uint32_t bOff = (lane & 7) * 144 + ((lane >> 3) & 1) * 16;

    float acc[8][4];
#pragma unroll
    for (int nt = 0; nt < 8; nt++)
#pragma unroll
        for (int j = 0; j < 4; j++) acc[nt][j] = 0.f;

#pragma unroll
    for (int kc = 0; kc < 4; kc++) {
        uint32_t bh[8][2], bl[8][2];
#pragma unroll
        for (int nt = 0; nt < 8; nt++) {
            uint32_t ba = sb + nt * 1152 + bOff + kc * 32;
            LDMX2(bh[nt], ba);
            LDMX2(bl[nt], ba + 9216);
        }
#pragma unroll
        for (int nt = 0; nt < 8; nt++) {
            MMA16816(acc[nt], ahi[kc], bh[nt]);
            MMA16816(acc[nt], ahi[kc], bl[nt]);
            MMA16816(acc[nt], alo[kc], bh[nt]);
        }
    }

    int n0 = nb + r0, n1 = n0 + 8;
#pragma unroll
    for (int nt = 0; nt < 8; nt++) {
        int col = nt * 8 + (lane & 3) * 2;
        float2 bb2 = *(const float2*)(bias + col);
        float2 o0, o1;
        o0.x = acc[nt][0] + bb2.x; o0.y = acc[nt][1] + bb2.y;
        o1.x = acc[nt][2] + bb2.x; o1.y = acc[nt][3] + bb2.y;
        *(float2*)(out + (size_t)n0 * 64 + col) = o0;
        *(float2*)(out + (size_t)n1 * 64 + col) = o1;
        if (n0 < Nv) {
            float2 s0; s0.x = acc[nt][0]; s0.y = acc[nt][1];
            *(float2*)(g_xlS + n0 * 64 + col) = s0;
        }
        if (n1 < Nv) {
            float2 s1; s1.x = acc[nt][2]; s1.y = acc[nt][3];
            *(float2*)(g_xlS + n1 * 64 + col) = s1;
        }
    }
    if (nb < Nv) {
        float ps0 = 0.f, pd0 = 0.f, ps1 = 0.f, pd1 = 0.f;
#pragma unroll
        for (int nt = 0; nt < 8; nt++) {
            int col = nt * 8 + (lane & 3) * 2;
            float2 a2 = *(const float2*)(attS + col);
            float2 d2 = *(const float2*)(attD + col);
            ps0 += acc[nt][0] * a2.x + acc[nt][1] * a2.y;
            pd0 += acc[nt][0] * d2.x + acc[nt][1] * d2.y;
            ps1 += acc[nt][2] * a2.x + acc[nt][3] * a2.y;
            pd1 += acc[nt][2] * d2.x + acc[nt][3] * d2.y;
        }
#pragma unroll
        for (int o = 1; o <= 2; o <<= 1) {
            ps0 += __shfl_xor_sync(0xffffffffu, ps0, o);
            pd0 += __shfl_xor_sync(0xffffffffu, pd0, o);
            ps1 += __shfl_xor_sync(0xffffffffu, ps1, o);
            pd1 += __shfl_xor_sync(0xffffffffu, pd1, o);
        }
        if ((lane & 3) == 0) {
            if (n0 < Nv) { g_aS[n0] = ps0; g_aD[n0] = pd0; }
            if (n1 < Nv) { g_aS[n1] = ps1; g_aD[n1] = pd1; }
        }
    }
}

// ------- bucket scatter + ea sum -------
__global__ void k_scatter(const int* __restrict__ ei, const float* __restrict__ ea) {
    int e = blockIdx.x * 256 + threadIdx.x;
    int d = ei[Ev + e];
    int s = ei[e];
    float v = ea[e];
    int pos = atomicAdd(&g_bcnt[d], 1);
    int idx = d * CAP + pos;
    g_bsrc[idx] = s;
    g_bval[idx] = v;
    g_bedge[idx] = e;
    float t = v;
#pragma unroll
    for (int o = 16; o; o >>= 1) t += __shfl_xor_sync(0xffffffffu, t, o);
    __shared__ float sh[8];
    if ((threadIdx.x & 31) == 0) sh[threadIdx.x >> 5] = t;
    __syncthreads();
    if (threadIdx.x < 8) {
        float w = sh[threadIdx.x];
#pragma unroll
        for (int o = 4; o; o >>= 1) w += __shfl_xor_sync(0xffu, w, o);
        if (threadIdx.x == 0) atomicAdd((float*)g_bcnt + Nv, w);
    }
}

// ------- per-destination softmax + aggregation: one warp per dst -------
__global__ void __launch_bounds__(256) k_dst(const float* __restrict__ W_edge,
                                             const float* __restrict__ attE,
                                             const float* __restrict__ bias,
                                             float* __restrict__ out) {
    int wIdx = threadIdx.x >> 5;
    int d = blockIdx.x * 8 + wIdx;
    int lane = threadIdx.x & 31;
    if (d >= Nv) return;
    float cv = W_edge[lane] * attE[lane] + W_edge[lane + 32] * attE[lane + 32];
#pragma unroll
    for (int o = 16; o; o >>= 1) cv += __shfl_xor_sync(0xffffffffu, cv, o);
    float meanC = ((const float*)g_bcnt)[Nv] * (1.f / (float)Ev) * cv;

    int cnt = g_bcnt[d];
    int base = d * CAP;
    float aDd = g_aD[d];
    float pSelf;
    {
        float xv = g_aS[d] + aDd + meanC;
        xv = xv > 0.f ? xv : 0.2f * xv;
        pSelf = __expf(xv);
    }
    __shared__ float sP[8][32];
    __shared__ int   sS[8][32];
    float a0x = 0.f, a0y = 0.f, a1x = 0.f, a1y = 0.f;
    float a2x = 0.f, a2y = 0.f, a3x = 0.f, a3y = 0.f;
    float psum = 0.f;
    for (int b0 = 0; b0 < cnt; b0 += 32) {
        int m = cnt - b0; if (m > 32) m = 32;
        if (lane < m) {
            int idx = base + b0 + lane;
            int s = g_bsrc[idx];
            float xv = g_aS[s] + aDd + g_bval[idx] * cv;
            xv = xv > 0.f ? xv : 0.2f * xv;
            float p = __expf(xv);
            psum += p;
            sP[wIdx][lane] = p;
            sS[wIdx][lane] = s;
            g_alphaC[idx] = p;                    // coalesced, for normalize pass
        }
        __syncwarp();
        int j = 0;
        for (; j + 4 <= m; j += 4) {
            float p0 = sP[wIdx][j],     p1 = sP[wIdx][j + 1];
            float p2 = sP[wIdx][j + 2], p3 = sP[wIdx][j + 3];
            int   q0 = sS[wIdx][j],     q1 = sS[wIdx][j + 1];
            int   q2 = sS[wIdx][j + 2], q3 = sS[wIdx][j + 3];
            float2 v0 = *(const float2*)(g_xlS + q0 * 64 + lane * 2);
            float2 v1 = *(const float2*)(g_xlS + q1 * 64 + lane * 2);
            float2 v2 = *(const float2*)(g_xlS + q2 * 64 + lane * 2);
            float2 v3 = *(const float2*)(g_xlS + q3 * 64 + lane * 2);
            a0x += p0 * v0.x; a0y += p0 * v0.y;
            a1x += p1 * v1.x; a1y += p1 * v1.y;
            a2x += p2 * v2.x; a2y += p2 * v2.y;
            a3x += p3 * v3.x; a3y += p3 * v3.y;
        }
        for (; j < m; j++) {
            float p0 = sP[wIdx][j];
            int   q0 = sS[wIdx][j];
            float2 v0 = *(const float2*)(g_xlS + q0 * 64 + lane * 2);
            a0x += p0 * v0.x; a0y += p0 * v0.y;
        }
        __syncwarp();
    }
    float accx = (a0x + a1x) + (a2x + a3x);
    float accy = (a0y + a1y) + (a2y + a3y);
#pragma unroll
    for (int o = 16; o; o >>= 1) psum += __shfl_xor_sync(0xffffffffu, psum, o);
    float denom = (float)Bv * psum + pSelf;
    float rd = 1.f / (denom + 1e-16f);
    float2 xs = *(const float2*)(g_xlS + d * 64 + lane * 2);
    float2 bb = *(const float2*)(bias + lane * 2);
    float2 o2;
    o2.x = ((float)Bv * accx + pSelf * xs.x) * rd + bb.x;
    o2.y = ((float)Bv * accy + pSelf * xs.y) * rd + bb.y;
    *(float2*)(out + (long long)d * 64 + lane * 2) = o2;
    if (lane == 0) g_selfNorm[d] = pSelf * rd;
    // normalize: coalesced load of p, scattered store to edge order
    for (int i = lane; i < cnt; i += 32) {
        int idx = base + i;
        g_alphaP[g_bedge[idx]] = g_alphaC[idx] * rd;
    }
}

// ------- tail float4 generators (shared logic) -------
__device__ __forceinline__ float4 tail_sd_val(const int* __restrict__ ei, int i) {
    float4 v;
    if (i < ETOTv) {
        if (i < BEv) {
            int e = i - (i / Ev) * Ev;
            v.x = (float)ei[e]; v.y = (float)ei[e + 1];
            v.z = (float)ei[e + 2]; v.w = (float)ei[e + 3];
        } else {
            float b0 = (float)(i - BEv);
            v.x = b0; v.y = b0 + 1.f; v.z = b0 + 2.f; v.w = b0 + 3.f;
        }
    } else {
        int k = i - ETOTv;
        if (k < BEv) {
            int e = k - (k / Ev) * Ev;
            v.x = (float)ei[Ev + e]; v.y = (float)ei[Ev + e + 1];
            v.z = (float)ei[Ev + e + 2]; v.w = (float)ei[Ev + e + 3];
        } else {
            float b0 = (float)(k - BEv);
            v.x = b0; v.y = b0 + 1.f; v.z = b0 + 2.f; v.w = b0 + 3.f;
        }
    }
    return v;
}

// tail part 1: src/dst rows. 4 float4 per thread (ILP).
__global__ void k_tail_sd(const int* __restrict__ ei, float* __restrict__ outTail) {
    int base4 = blockIdx.x * 1024 + threadIdx.x;     // float4 index
    float4 v[4];
    int idx[4];
#pragma unroll
    for (int k = 0; k < 4; k++) {
        idx[k] = base4 + k * 256;
        int i = idx[k] * 4;
        if (i < 2 * ETOTv) v[k] = tail_sd_val(ei, i);
    }
#pragma unroll
    for (int k = 0; k < 4; k++) {
        int i = idx[k] * 4;
        if (i < 2 * ETOTv) *(float4*)(outTail + i) = v[k];
    }
}

__device__ __forceinline__ float4 tail_alpha_val(int i) {
    float4 v;
    if (i < BEv) {
        int e = i - (i / Ev) * Ev;
        v = *(const float4*)(g_alphaP + e);
    } else {
        int d = i - BEv;
        if (d + 3 < Nv) {
            v.x = g_selfNorm[d]; v.y = g_selfNorm[d + 1];
            v.z = g_selfNorm[d + 2]; v.w = g_selfNorm[d + 3];
        } else {
            v.x = (d     < Nv) ? g_selfNorm[d]     : 1.0f;
            v.y = (d + 1 < Nv) ? g_selfNorm[d + 1] : 1.0f;
            v.z = (d + 2 < Nv) ? g_selfNorm[d + 2] : 1.0f;
            v.w = (d + 3 < Nv) ? g_selfNorm[d + 3] : 1.0f;
        }
    }
    return v;
}

// tail part 2: alpha. 4 float4 per thread (ILP).
__global__ void k_tail_alpha(float* __restrict__ outA, int totalA) {
    int base4 = blockIdx.x * 1024 + threadIdx.x;
    float4 v[4];
    int idx[4];
#pragma unroll
    for (int k = 0; k < 4; k++) {
        idx[k] = base4 + k * 256;
        int i = idx[k] * 4;
        if (i < totalA) v[k] = tail_alpha_val(i);
    }
#pragma unroll
    for (int k = 0; k < 4; k++) {
        int i = idx[k] * 4;
        if (i < totalA) *(float4*)(outA + i) = v[k];
    }
}

// ---------------- launch ----------------
extern "C" void kernel_launch(void* const* d_in, const int* in_sizes, int n_in,
                              void* d_out, int out_size) {
    const float* data   = (const float*)d_in[0];
    const int*   ei     = (const int*)  d_in[1];
    const float* ea     = (const float*)d_in[2];
    const float* W      = (const float*)d_in[3];
    const float* W_edge = (const float*)d_in[4];
    const float* attS   = (const float*)d_in[5];
    const float* attD   = (const float*)d_in[6];
    const float* attE   = (const float*)d_in[7];
    const float* bias   = (const float*)d_in[8];
    float* out = (float*)d_out;

    static cudaStream_t sB = nullptr, sC = nullptr, sD = nullptr;
    static cudaEvent_t eFork = nullptr, eB = nullptr, eC = nullptr, eW = nullptr, eD = nullptr;
    if (!sB) {
        cudaStreamCreateWithFlags(&sB, cudaStreamNonBlocking);
        cudaStreamCreateWithFlags(&sC, cudaStreamNonBlocking);
        cudaStreamCreateWithFlags(&sD, cudaStreamNonBlocking);
        cudaEventCreateWithFlags(&eFork, cudaEventDisableTiming);
        cudaEventCreateWithFlags(&eB, cudaEventDisableTiming);
        cudaEventCreateWithFlags(&eC, cudaEventDisableTiming);
        cudaEventCreateWithFlags(&eW, cudaEventDisableTiming);
        cudaEventCreateWithFlags(&eD, cudaEventDisableTiming);
    }

    void* bcntAddr = nullptr;
    cudaGetSymbolAddress(&bcntAddr, g_bcnt);

    cudaEventRecord(eFork, 0);
    cudaStreamWaitEvent(sB, eFork, 0);
    cudaStreamWaitEvent(sC, eFork, 0);

    // side chain: bucket CSR build
    cudaMemsetAsync(bcntAddr, 0, (Nv + 2) * sizeof(int), sB);
    k_scatter<<<NPART, 256, 0, sB>>>(ei, ea);
    cudaEventRecord(eB, sB);

    // tail src/dst rows (independent): 1.32M float4 / 1024 per block
    if (out_size > OUT_MAIN) {
        int nblk = (2 * ETOTv / 4 + 1023) / 1024;
        k_tail_sd<<<nblk, 256, 0, sC>>>(ei, out + OUT_MAIN);
    }
    cudaEventRecord(eC, sC);

    // W image, then head (main) and rest (sD) concurrently
    k_wconv<<<8, 256>>>(W);
    cudaEventRecord(eW, 0);
    cudaStreamWaitEvent(sD, eW, 0);
    k_gemm<<<BNv / 128 - HEADBLKS, 256, 0, sD>>>(data, bias, attS, attD, out, HEADBLKS);
    cudaEventRecord(eD, sD);
    k_gemm<<<HEADBLKS, 256>>>(data, bias, attS, attD, out, 0);

    // main: wait CSR, then softmax/aggregate (overlaps gemm_rest), alpha tail
    cudaStreamWaitEvent(0, eB, 0);
    k_dst<<<(Nv + 7) / 8, 256>>>(W_edge, attE, bias, out);

    if (out_size > OUT_MAIN) {
        int totalA = out_size - OUT_MAIN - 2 * ETOTv;
        if (totalA > 0) {
            int nblk = ((totalA + 3) / 4 + 1023) / 1024;
            k_tail_alpha<<<nblk, 256>>>(out + OUT_MAIN + 2 * ETOTv, totalA);
        }
    }

    cudaStreamWaitEvent(0, eC, 0);
    cudaStreamWaitEvent(0, eD, 0);
}

// round 13
// speedup vs baseline: 1.9823x; 1.0430x over previous
#include <cuda_runtime.h>
#include <cuda_bf16.h>
#include <cstdint>

#define Bv   16
#define Nv   5000
#define Ev   160000
#define BNv  80000
#define BEv  2560000
#define ETOTv 2640000
#define OUT_MAIN 5120000   // BNv * 64
#define NPART 625          // Ev / 256
#define CAP  128           // bucket capacity per destination
#define HEADBLKS 40        // blocks covering nodes < Nv (40*128 = 5120)

// ---------------- scratch (static __device__, no allocs) ----------------
__device__ float  g_xlS[Nv * 64];
__device__ float  g_aS[Nv];
__device__ float  g_aD[Nv];
__device__ int    g_bcnt[Nv + 2];     // [Nv] reused as float sum(ea)
__device__ float2 g_bsv[Nv * CAP];    // packed (src-as-float-bits, ea)
__device__ int    g_bedge[Nv * CAP];
__device__ float  g_alphaC[Nv * CAP]; // unnormalized p, CSR-slot order
__device__ float  g_alphaP[Ev];       // normalized alpha per unique edge
__device__ float  g_selfNorm[Nv];
__device__ uint4  g_Wimg[1152];       // 18432B: W_hi [64][72]bf16 | W_lo [64][72]bf16

// ---------------- helpers ----------------
__device__ __forceinline__ uint32_t smem_to_u32(const void* p) {
    uint32_t a;
    asm("{ .reg .u64 t; cvta.to.shared.u64 t, %1; cvt.u32.u64 %0, t; }" : "=r"(a) : "l"(p));
    return a;
}
__device__ __forceinline__ uint32_t pack_hi(float2 v) {
    __nv_bfloat162 h = __float22bfloat162_rn(v);
    return *(uint32_t*)&h;
}
__device__ __forceinline__ uint32_t pack_lo(float2 v, uint32_t hi) {
    __nv_bfloat162 h = *(__nv_bfloat162*)&hi;
    float2 hf = __bfloat1622float2(h);
    float2 r; r.x = v.x - hf.x; r.y = v.y - hf.y;
    __nv_bfloat162 l = __float22bfloat162_rn(r);
    return *(uint32_t*)&l;
}
#define LDMX2(r, a) \
    asm volatile("ldmatrix.sync.aligned.m8n8.x2.shared.b16 {%0,%1}, [%2];" \
        : "=r"((r)[0]), "=r"((r)[1]) : "r"(a))
#define MMA16816(c, a, b) \
    asm volatile("mma.sync.aligned.m16n8k16.row.col.f32.bf16.bf16.f32 " \
        "{%0,%1,%2,%3}, {%4,%5,%6,%7}, {%8,%9}, {%0,%1,%2,%3};" \
        : "+f"((c)[0]), "+f"((c)[1]), "+f"((c)[2]), "+f"((c)[3]) \
        : "r"((a)[0]), "r"((a)[1]), "r"((a)[2]), "r"((a)[3]), "r"((b)[0]), "r"((b)[1]))

// ---------------- W -> bf16 hi/lo image [64 rows][72 bf16] ----------------
__global__ void k_wconv(const float* __restrict__ W) {
    int p = blockIdx.x * 256 + threadIdx.x;          // 8 blocks x 256 = 2048
    char* img = (char*)g_Wimg;
    int c = p >> 5, cp = p & 31;
    float2 v = *(const float2*)(W + c * 64 + cp * 2);
    uint32_t hu = pack_hi(v);
    uint32_t lu = pack_lo(v, hu);
    *(unsigned*)(img + c * 144 + cp * 4) = hu;
    *(unsigned*)(img + 9216 + c * 144 + cp * 4) = lu;
}

// ---- tensor GEMM: A direct-to-register, B ldmatrix, batched loads ----
__global__ void __launch_bounds__(256, 2) k_gemm(const float* __restrict__ x,
                                                 const float* __restrict__ bias,
                                                 const float* __restrict__ attS,
                                                 const float* __restrict__ attD,
                                                 float* __restrict__ out,
                                                 int blockOff) {
    __shared__ char smB[18432];
    int tid = threadIdx.x, wid = tid >> 5, lane = tid & 31;
    int nb = (blockIdx.x + blockOff) * 128;

    {
        uint4* dst = (uint4*)smB;
#pragma unroll
        for (int i = 0; i < 5; i++) {
            int j = tid + i * 256;
            if (j < 1152) dst[j] = g_Wimg[j];
        }
    }

    int r0 = wid * 16 + (lane >> 2);
    const float* xr = x + (size_t)(nb + r0) * 64 + (lane & 3) * 2;
    float2 v[4][4];
#pragma unroll
    for (int kc = 0; kc < 4; kc++) {
        v[kc][0] = *(const float2*)(xr + kc * 16);
        v[kc][1] = *(const float2*)(xr + 8 * 64 + kc * 16);
        v[kc][2] = *(const float2*)(xr + kc * 16 + 8);
        v[kc][3] = *(const float2*)(xr + 8 * 64 + kc * 16 + 8);
    }
    uint32_t ahi[4][4], alo[4][4];
#pragma unroll
    for (int kc = 0; kc < 4; kc++)
#pragma unroll
        for (int j = 0; j < 4; j++) {
            ahi[kc][j] = pack_hi(v[kc][j]);
            alo[kc][j] = pack_lo(v[kc][j], ahi[kc][j]);
        }
    __syncthreads();

    uint32_t sb = smem_to_u32(smB);
    uint32_t bOff = (lane & 7) * 144 + ((lane >> 3) & 1) * 16;

    float acc[8][4];
#pragma unroll
    for (int nt = 0; nt < 8; nt++)
#pragma unroll
        for (int j = 0; j < 4; j++) acc[nt][j] = 0.f;

#pragma unroll
    for (int kc = 0; kc < 4; kc++) {
        uint32_t bh[8][2], bl[8][2];
#pragma unroll
        for (int nt = 0; nt < 8; nt++) {
            uint32_t ba = sb + nt * 1152 + bOff + kc * 32;
            LDMX2(bh[nt], ba);
            LDMX2(bl[nt], ba + 9216);
        }
#pragma unroll
        for (int nt = 0; nt < 8; nt++) {
            MMA16816(acc[nt], ahi[kc], bh[nt]);
            MMA16816(acc[nt], ahi[kc], bl[nt]);
            MMA16816(acc[nt], alo[kc], bh[nt]);
        }
    }

    int n0 = nb + r0, n1 = n0 + 8;
#pragma unroll
    for (int nt = 0; nt < 8; nt++) {
        int col = nt * 8 + (lane & 3) * 2;
        float2 bb2 = *(const float2*)(bias + col);
        float2 o0, o1;
        o0.x = acc[nt][0] + bb2.x; o0.y = acc[nt][1] + bb2.y;
        o1.x = acc[nt][2] + bb2.x; o1.y = acc[nt][3] + bb2.y;
        *(float2*)(out + (size_t)n0 * 64 + col) = o0;
        *(float2*)(out + (size_t)n1 * 64 + col) = o1;
        if (n0 < Nv) {
            float2 s0; s0.x = acc[nt][0]; s0.y = acc[nt][1];
            *(float2*)(g_xlS + n0 * 64 + col) = s0;
        }
        if (n1 < Nv) {
            float2 s1; s1.x = acc[nt][2]; s1.y = acc[nt][3];
            *(float2*)(g_xlS + n1 * 64 + col) = s1;
        }
    }
    if (nb < Nv) {
        float ps0 = 0.f, pd0 = 0.f, ps1 = 0.f, pd1 = 0.f;
#pragma unroll
        for (int nt = 0; nt < 8; nt++) {
            int col = nt * 8 + (lane & 3) * 2;
            float2 a2 = *(const float2*)(attS + col);
            float2 d2 = *(const float2*)(attD + col);
            ps0 += acc[nt][0] * a2.x + acc[nt][1] * a2.y;
            pd0 += acc[nt][0] * d2.x + acc[nt][1] * d2.y;
            ps1 += acc[nt][2] * a2.x + acc[nt][3] * a2.y;
            pd1 += acc[nt][2] * d2.x + acc[nt][3] * d2.y;
        }
#pragma unroll
        for (int o = 1; o <= 2; o <<= 1) {
            ps0 += __shfl_xor_sync(0xffffffffu, ps0, o);
            pd0 += __shfl_xor_sync(0xffffffffu, pd0, o);
            ps1 += __shfl_xor_sync(0xffffffffu, ps1, o);
            pd1 += __shfl_xor_sync(0xffffffffu, pd1, o);
        }
        if ((lane & 3) == 0) {
            if (n0 < Nv) { g_aS[n0] = ps0; g_aD[n0] = pd0; }
            if (n1 < Nv) { g_aS[n1] = ps1; g_aD[n1] = pd1; }
        }
    }
}

// ------- bucket scatter + ea sum (packed payload) -------
__global__ void k_scatter(const int* __restrict__ ei, const float* __restrict__ ea) {
    int e = blockIdx.x * 256 + threadIdx.x;
    int d = ei[Ev + e];
    int s = ei[e];
    float v = ea[e];
    int pos = atomicAdd(&g_bcnt[d], 1);
    int idx = d * CAP + pos;
    float2 sv; sv.x = __int_as_float(s); sv.y = v;
    g_bsv[idx] = sv;
    g_bedge[idx] = e;
    float t = v;
#pragma unroll
    for (int o = 16; o; o >>= 1) t += __shfl_xor_sync(0xffffffffu, t, o);
    __shared__ float sh[8];
    if ((threadIdx.x & 31) == 0) sh[threadIdx.x >> 5] = t;
    __syncthreads();
    if (threadIdx.x < 8) {
        float w = sh[threadIdx.x];
#pragma unroll
        for (int o = 4; o; o >>= 1) w += __shfl_xor_sync(0xffu, w, o);
        if (threadIdx.x == 0) atomicAdd((float*)g_bcnt + Nv, w);
    }
}

// ------- per-destination softmax + aggregation: one warp per dst -------
__global__ void __launch_bounds__(256) k_dst(const float* __restrict__ W_edge,
                                             const float* __restrict__ attE,
                                             const float* __restrict__ bias,
                                             float* __restrict__ out) {
    int wIdx = threadIdx.x >> 5;
    int d = blockIdx.x * 8 + wIdx;
    int lane = threadIdx.x & 31;
    float cv = W_edge[lane] * attE[lane] + W_edge[lane + 32] * attE[lane + 32];
#pragma unroll
    for (int o = 16; o; o >>= 1) cv += __shfl_xor_sync(0xffffffffu, cv, o);
    float meanC = ((const float*)g_bcnt)[Nv] * (1.f / (float)Ev) * cv;

    int cnt = g_bcnt[d];
    int base = d * CAP;
    float aDd = g_aD[d];
    float pSelf;
    {
        float xv = g_aS[d] + aDd + meanC;
        xv = xv > 0.f ? xv : 0.2f * xv;
        pSelf = __expf(xv);
    }
    __shared__ float sP[8][32];
    __shared__ int   sS[8][32];
    float a0x = 0.f, a0y = 0.f, a1x = 0.f, a1y = 0.f;
    float a2x = 0.f, a2y = 0.f, a3x = 0.f, a3y = 0.f;
    float psum = 0.f;
    for (int b0 = 0; b0 < cnt; b0 += 32) {
        int m = cnt - b0; if (m > 32) m = 32;
        if (lane < m) {
            int idx = base + b0 + lane;
            float2 sv = g_bsv[idx];
            int s = __float_as_int(sv.x);
            float xv = g_aS[s] + aDd + sv.y * cv;
            xv = xv > 0.f ? xv : 0.2f * xv;
            float p = __expf(xv);
            psum += p;
            sP[wIdx][lane] = p;
            sS[wIdx][lane] = s;
            g_alphaC[idx] = p;                    // coalesced, for normalize pass
        }
        __syncwarp();
        int j = 0;
        for (; j + 4 <= m; j += 4) {
            float p0 = sP[wIdx][j],     p1 = sP[wIdx][j + 1];
            float p2 = sP[wIdx][j + 2], p3 = sP[wIdx][j + 3];
            int   q0 = sS[wIdx][j],     q1 = sS[wIdx][j + 1];
            int   q2 = sS[wIdx][j + 2], q3 = sS[wIdx][j + 3];
            float2 v0 = *(const float2*)(g_xlS + q0 * 64 + lane * 2);
            float2 v1 = *(const float2*)(g_xlS + q1 * 64 + lane * 2);
            float2 v2 = *(const float2*)(g_xlS + q2 * 64 + lane * 2);
            float2 v3 = *(const float2*)(g_xlS + q3 * 64 + lane * 2);
            a0x += p0 * v0.x; a0y += p0 * v0.y;
            a1x += p1 * v1.x; a1y += p1 * v1.y;
            a2x += p2 * v2.x; a2y += p2 * v2.y;
            a3x += p3 * v3.x; a3y += p3 * v3.y;
        }
        for (; j < m; j++) {
            float p0 = sP[wIdx][j];
            int   q0 = sS[wIdx][j];
            float2 v0 = *(const float2*)(g_xlS + q0 * 64 + lane * 2);
            a0x += p0 * v0.x; a0y += p0 * v0.y;
        }
        __syncwarp();
    }
    float accx = (a0x + a1x) + (a2x + a3x);
    float accy = (a0y + a1y) + (a2y + a3y);
#pragma unroll
    for (int o = 16; o; o >>= 1) psum += __shfl_xor_sync(0xffffffffu, psum, o);
    float denom = (float)Bv * psum + pSelf;
    float rd = 1.f / (denom + 1e-16f);
    float2 xs = *(const float2*)(g_xlS + d * 64 + lane * 2);
    float2 bb = *(const float2*)(bias + lane * 2);
    float2 o2;
    o2.x = ((float)Bv * accx + pSelf * xs.x) * rd + bb.x;
    o2.y = ((float)Bv * accy + pSelf * xs.y) * rd + bb.y;
    *(float2*)(out + (long long)d * 64 + lane * 2) = o2;
    if (lane == 0) g_selfNorm[d] = pSelf * rd;
    for (int i = lane; i < cnt; i += 32) {
        int idx = base + i;
        g_alphaP[g_bedge[idx]] = g_alphaC[idx] * rd;
    }
}

// ------- tail float4 generators -------
__device__ __forceinline__ float4 tail_sd_val(const int* __restrict__ ei, int i) {
    float4 v;
    if (i < ETOTv) {
        if (i < BEv) {
            int e = i - (i / Ev) * Ev;
            v.x = (float)ei[e]; v.y = (float)ei[e + 1];
            v.z = (float)ei[e + 2]; v.w = (float)ei[e + 3];
        } else {
            float b0 = (float)(i - BEv);
            v.x = b0; v.y = b0 + 1.f; v.z = b0 + 2.f; v.w = b0 + 3.f;
        }
    } else {
        int k = i - ETOTv;
        if (k < BEv) {
            int e = k - (k / Ev) * Ev;
            v.x = (float)ei[Ev + e]; v.y = (float)ei[Ev + e + 1];
            v.z = (float)ei[Ev + e + 2]; v.w = (float)ei[Ev + e + 3];
        } else {
            float b0 = (float)(k - BEv);
            v.x = b0; v.y = b0 + 1.f; v.z = b0 + 2.f; v.w = b0 + 3.f;
        }
    }
    return v;
}

__global__ void k_tail_sd(const int* __restrict__ ei, float* __restrict__ outTail) {
    int base4 = blockIdx.x * 1024 + threadIdx.x;
    float4 v[4];
    int idx[4];
#pragma unroll
    for (int k = 0; k < 4; k++) {
        idx[k] = base4 + k * 256;
        int i = idx[k] * 4;
        if (i < 2 * ETOTv) v[k] = tail_sd_val(ei, i);
    }
#pragma unroll
    for (int k = 0; k < 4; k++) {
        int i = idx[k] * 4;
        if (i < 2 * ETOTv) *(float4*)(outTail + i) = v[k];
    }
}

__device__ __forceinline__ float4 tail_alpha_val(int i) {
    float4 v;
    if (i < BEv) {
        int e = i - (i / Ev) * Ev;
        v = *(const float4*)(g_alphaP + e);
    } else {
        int d = i - BEv;
        if (d + 3 < Nv) {
            v.x = g_selfNorm[d]; v.y = g_selfNorm[d + 1];
            v.z = g_selfNorm[d + 2]; v.w = g_selfNorm[d + 3];
        } else {
            v.x = (d     < Nv) ? g_selfNorm[d]     : 1.0f;
            v.y = (d + 1 < Nv) ? g_selfNorm[d + 1] : 1.0f;
            v.z = (d + 2 < Nv) ? g_selfNorm[d + 2] : 1.0f;
            v.w = (d + 3 < Nv) ? g_selfNorm[d + 3] : 1.0f;
        }
    }
    return v;
}

__global__ void k_tail_alpha(float* __restrict__ outA, int totalA) {
    int base4 = blockIdx.x * 1024 + threadIdx.x;
    float4 v[4];
    int idx[4];
#pragma unroll
    for (int k = 0; k < 4; k++) {
        idx[k] = base4 + k * 256;
        int i = idx[k] * 4;
        if (i < totalA) v[k] = tail_alpha_val(i);
    }
#pragma unroll
    for (int k = 0; k < 4; k++) {
        int i = idx[k] * 4;
        if (i < totalA) *(float4*)(outA + i) = v[k];
    }
}

// ---------------- launch ----------------
extern "C" void kernel_launch(void* const* d_in, const int* in_sizes, int n_in,
                              void* d_out, int out_size) {
    const float* data   = (const float*)d_in[0];
    const int*   ei     = (const int*)  d_in[1];
    const float* ea     = (const float*)d_in[2];
    const float* W      = (const float*)d_in[3];
    const float* W_edge = (const float*)d_in[4];
    const float* attS   = (const float*)d_in[5];
    const float* attD   = (const float*)d_in[6];
    const float* attE   = (const float*)d_in[7];
    const float* bias   = (const float*)d_in[8];
    float* out = (float*)d_out;

    static cudaStream_t sB = nullptr, sC = nullptr, sD = nullptr;
    static cudaEvent_t eFork = nullptr, eB = nullptr, eC = nullptr, eW = nullptr, eD = nullptr;
    if (!sB) {
        int prLo = 0, prHi = 0;
        cudaDeviceGetStreamPriorityRange(&prLo, &prHi);   // prLo = least priority
        cudaStreamCreateWithFlags(&sB, cudaStreamNonBlocking);
        cudaStreamCreateWithFlags(&sC, cudaStreamNonBlocking);
        cudaStreamCreateWithPriority(&sD, cudaStreamNonBlocking, prLo); // bulk gemm: lowest prio
        cudaEventCreateWithFlags(&eFork, cudaEventDisableTiming);
        cudaEventCreateWithFlags(&eB, cudaEventDisableTiming);
        cudaEventCreateWithFlags(&eC, cudaEventDisableTiming);
        cudaEventCreateWithFlags(&eW, cudaEventDisableTiming);
        cudaEventCreateWithFlags(&eD, cudaEventDisableTiming);
    }

    void* bcntAddr = nullptr;
    cudaGetSymbolAddress(&bcntAddr, g_bcnt);

    cudaEventRecord(eFork, 0);
    cudaStreamWaitEvent(sB, eFork, 0);
    cudaStreamWaitEvent(sC, eFork, 0);

    // side chain: bucket CSR build
    cudaMemsetAsync(bcntAddr, 0, (Nv + 2) * sizeof(int), sB);
    k_scatter<<<NPART, 256, 0, sB>>>(ei, ea);
    cudaEventRecord(eB, sB);

    // tail src/dst rows (independent)
    if (out_size > OUT_MAIN) {
        int nblk = (2 * ETOTv / 4 + 1023) / 1024;
        k_tail_sd<<<nblk, 256, 0, sC>>>(ei, out + OUT_MAIN);
    }
    cudaEventRecord(eC, sC);

    // W image, then HEAD FIRST (main), rest second (sD, low priority)
    k_wconv<<<8, 256>>>(W);
    cudaEventRecord(eW, 0);
    k_gemm<<<HEADBLKS, 256>>>(data, bias, attS, attD, out, 0);
    cudaStreamWaitEvent(sD, eW, 0);
    k_gemm<<<BNv / 128 - HEADBLKS, 256, 0, sD>>>(data, bias, attS, attD, out, HEADBLKS);
    cudaEventRecord(eD, sD);

    // main: wait CSR, then softmax/aggregate (overlaps gemm_rest), alpha tail
    cudaStreamWaitEvent(0, eB, 0);
    k_dst<<<Nv / 8, 256>>>(W_edge, attE, bias, out);

    if (out_size > OUT_MAIN) {
        int totalA = out_size - OUT_MAIN - 2 * ETOTv;
        if (totalA > 0) {
            int nblk = ((totalA + 3) / 4 + 1023) / 1024;
            k_tail_alpha<<<nblk, 256>>>(out + OUT_MAIN + 2 * ETOTv, totalA);
        }
    }

    cudaStreamWaitEvent(0, eC, 0);
    cudaStreamWaitEvent(0, eD, 0);
}